// round 12
// baseline (speedup 1.0000x reference)
#include <cuda_runtime.h>
#include <cstdint>
#include <cstddef>

typedef unsigned long long u64;

#define BB 64
#define TT 512
#define DD 256
#define GG 1024   // 4*D
#define CLS 8     // CTAs per cluster
#define NPROD 80  // producer CTAs
#define NTILES 4096

// ---------------- scratch (device globals; no runtime allocation) ----------
__device__ float d_xs[(size_t)BB * TT * GG];
__device__ float d_h[(size_t)BB * TT * DD];
__device__ float d_snorm[BB * DD];
__device__ float d_WpT[DD * DD];
__device__ float d_WxT[DD * DD];
__device__ float d_WfT[DD * DD];
__device__ float d_z[BB * TT];
__device__ float d_rp[BB * 8 * DD];
__device__ uint32_t d_flags[8];      // per-64-timestep-chunk tile counters

// ---------------- fast activations (MUFU.TANH) -------------------------------
__device__ __forceinline__ float ftanhf(float x) {
    float r; asm("tanh.approx.f32 %0, %1;" : "=f"(r) : "f"(x)); return r;
}
__device__ __forceinline__ float fsig(float x) {
    return fmaf(0.5f, ftanhf(0.5f * x), 0.5f);
}

__device__ __forceinline__ uint32_t ctarank() {
    uint32_t r; asm("mov.u32 %0, %%cluster_ctarank;" : "=r"(r)); return r;
}
__device__ __forceinline__ void cluster_sync() {
    asm volatile("barrier.cluster.arrive.aligned;\n\tbarrier.cluster.wait.aligned;" ::: "memory");
}
__device__ __forceinline__ uint32_t mapa_sh(uint32_t laddr, uint32_t rank) {
    uint32_t ra; asm("mapa.shared::cluster.u32 %0, %1, %2;" : "=r"(ra) : "r"(laddr), "r"(rank));
    return ra;
}
__device__ __forceinline__ void mbar_init(uint32_t addr, uint32_t cnt) {
    asm volatile("mbarrier.init.shared.b64 [%0], %1;" :: "r"(addr), "r"(cnt) : "memory");
}
__device__ __forceinline__ void mbar_expect(uint32_t addr, uint32_t bytes) {
    asm volatile("mbarrier.arrive.expect_tx.shared.b64 _, [%0], %1;"
                 :: "r"(addr), "r"(bytes) : "memory");
}
__device__ __forceinline__ void st_async_v4(uint32_t raddr, float4 v, uint32_t rmbar) {
    asm volatile(
        "st.async.shared::cluster.mbarrier::complete_tx::bytes.v4.b32 "
        "[%0], {%1,%2,%3,%4}, [%5];"
        :: "r"(raddr),
           "r"(__float_as_uint(v.x)), "r"(__float_as_uint(v.y)),
           "r"(__float_as_uint(v.z)), "r"(__float_as_uint(v.w)),
           "r"(rmbar) : "memory");
}
__device__ __forceinline__ void mbar_wait(uint32_t addr, uint32_t parity) {
    asm volatile(
        "{\n\t.reg .pred P;\n\t"
        "WL_%=:\n\t"
        "mbarrier.try_wait.parity.acquire.cluster.shared::cta.b64 P, [%0], %1, 0x989680;\n\t"
        "@!P bra WL_%=;\n\t"
        "}" :: "r"(addr), "r"(parity) : "memory");
}
__device__ __forceinline__ void flag_release_add(uint32_t* p) {
    asm volatile("red.release.gpu.global.add.u32 [%0], %1;" :: "l"(p), "r"(1u) : "memory");
}
__device__ __forceinline__ uint32_t flag_acquire_ld(const uint32_t* p) {
    uint32_t v;
    asm volatile("ld.acquire.gpu.u32 %0, [%1];" : "=r"(v) : "l"(p) : "memory");
    return v;
}

// ---------------- packed f32x2 helpers --------------------------------------
__device__ __forceinline__ u64 dup2(float v) {
    u64 r; asm("mov.b64 %0, {%1, %1};" : "=l"(r) : "f"(v)); return r;
}
__device__ __forceinline__ void fma2(u64& d, u64 a, u64 b) {
    asm("fma.rn.f32x2 %0, %1, %2, %0;" : "+l"(d) : "l"(a), "l"(b));
}
__device__ __forceinline__ void up2(float& lo, float& hi, u64 v) {
    asm("mov.b64 {%0, %1}, %2;" : "=f"(lo), "=f"(hi) : "l"(v));
}

// ---------------- prep (also zeroes xs progress flags) ----------------------
__global__ void k_prep(const float* __restrict__ W_p,
                       const float* __restrict__ W_x, const float* __restrict__ W_f) {
    int i = blockIdx.x * 256 + threadIdx.x;
    if (i < 8) d_flags[i] = 0u;
    if (i < DD * DD) {
        int e = i / DD, d = i % DD;
        d_WpT[d * DD + e] = W_p[i];
        d_WxT[d * DD + e] = W_x[i];
        d_WfT[d * DD + e] = W_f[i];
    }
}

// ---------------- s_norm ----------------------------------------------------
__global__ void k_snorm(const int* __restrict__ s, const float* __restrict__ emb) {
    int d = threadIdx.x;
    float sum = 0.f, sq = 0.f;
    for (int b = 0; b < BB; b++) {
        float v = emb[(size_t)s[b] * DD + d];
        sum += v; sq += v * v;
    }
    float mu  = sum * (1.f / BB);
    float var = sq * (1.f / BB) - mu * mu;
    float inv = rsqrtf(var + 1e-5f);
    for (int b = 0; b < BB; b++) {
        float v = emb[(size_t)s[b] * DD + d];
        d_snorm[b * DD + d] = (v - mu) * inv;
    }
}

// ---------------- xs producer: 64x128 tiles, t-chunk-major -------------------
__device__ void produce_xs(int p, const int* __restrict__ x,
                           const float* __restrict__ emb,
                           const float* __restrict__ w_ih,
                           const float* __restrict__ bl,
                           float* smem) {
    float* As = smem;          // [16][64]
    float* Bs = smem + 1024;   // [16][128]
    int tid = threadIdx.x;
    int tx = tid & 15, ty = tid >> 4;     // tx: 8-col group, ty: 4-row group
    int ar = tid >> 2, akc = (tid & 3) * 4;
    int br = tid >> 1, bkc = (tid & 1) * 8;

    for (int tile = p; tile < NTILES; tile += NPROD) {
        int tc  = tile >> 9;          // 64-timestep chunk 0..7
        int rem = tile & 511;
        int bt  = rem >> 3;           // batch 0..63
        int nt  = rem & 7;            // n-tile 0..7
        int m0 = bt * 512 + tc * 64;
        int n0 = nt * 128;

        const float* arow = emb + (size_t)x[m0 + ar] * DD;
        const float* brow = w_ih + (size_t)(n0 + br) * DD;

        u64 acc2[4][4];
#pragma unroll
        for (int i = 0; i < 4; i++)
#pragma unroll
            for (int j = 0; j < 4; j++) acc2[i][j] = 0ull;

        for (int k0 = 0; k0 < DD; k0 += 16) {
            float4 av = *(const float4*)(arow + k0 + akc);
            float4 b0v = *(const float4*)(brow + k0 + bkc);
            float4 b1v = *(const float4*)(brow + k0 + bkc + 4);
            As[(akc + 0) * 64 + ar] = av.x;
            As[(akc + 1) * 64 + ar] = av.y;
            As[(akc + 2) * 64 + ar] = av.z;
            As[(akc + 3) * 64 + ar] = av.w;
            Bs[(bkc + 0) * 128 + br] = b0v.x;
            Bs[(bkc + 1) * 128 + br] = b0v.y;
            Bs[(bkc + 2) * 128 + br] = b0v.z;
            Bs[(bkc + 3) * 128 + br] = b0v.w;
            Bs[(bkc + 4) * 128 + br] = b1v.x;
            Bs[(bkc + 5) * 128 + br] = b1v.y;
            Bs[(bkc + 6) * 128 + br] = b1v.z;
            Bs[(bkc + 7) * 128 + br] = b1v.w;
            __syncthreads();
#pragma unroll
            for (int k = 0; k < 16; k++) {
                float4 a = *(const float4*)&As[k * 64 + ty * 4];
                const u64* bp = (const u64*)&Bs[k * 128 + tx * 8];
                u64 bb0 = bp[0], bb1 = bp[1], bb2 = bp[2], bb3 = bp[3];
                float aa[4] = {a.x, a.y, a.z, a.w};
#pragma unroll
                for (int i = 0; i < 4; i++) {
                    u64 ai = dup2(aa[i]);
                    fma2(acc2[i][0], ai, bb0);
                    fma2(acc2[i][1], ai, bb1);
                    fma2(acc2[i][2], ai, bb2);
                    fma2(acc2[i][3], ai, bb3);
                }
            }
            __syncthreads();
        }
        int col = n0 + tx * 8;
        float4 blv0 = *(const float4*)(bl + col);
        float4 blv1 = *(const float4*)(bl + col + 4);
#pragma unroll
        for (int i = 0; i < 4; i++) {
            size_t row = m0 + ty * 4 + i;
            float c0, c1, c2, c3, c4, c5, c6, c7;
            up2(c0, c1, acc2[i][0]);
            up2(c2, c3, acc2[i][1]);
            up2(c4, c5, acc2[i][2]);
            up2(c6, c7, acc2[i][3]);
            float* op = d_xs + row * GG + col;
            *(float4*)op       = make_float4(c0 + blv0.x, c1 + blv0.y, c2 + blv0.z, c3 + blv0.w);
            *(float4*)(op + 4) = make_float4(c4 + blv1.x, c5 + blv1.y, c6 + blv1.z, c7 + blv1.w);
        }
        __syncthreads();
        if (tid == 0) flag_release_add(&d_flags[tc]);
    }
}

// ------- main kernel: 8 LSTM clusters (CTA 0..63) + 80 producers (64..143) ---
#define OFF_PSMA  32768
#define OFF_PSMB  (32768 + 4096)
#define OFF_HB    (32768 + 8192)
#define OFF_HST   (OFF_HB + 4096)
#define OFF_MBAR  (OFF_HST + 256)
#define LSTM_SMEM_BYTES ((OFF_MBAR + 8) * 4)
#define PHASE_BYTES 4096u

__device__ __forceinline__ void lstm_mm(const float* hcur,
                                        const u64 (&wreg)[8][4][2],
                                        float* psm, int wid, int lane) {
    u64 acc2[2][4];
#pragma unroll
    for (int b = 0; b < 4; b++) { acc2[0][b] = 0ull; acc2[1][b] = 0ull; }
    const float* hp = hcur + wid * 32;
#pragma unroll
    for (int i4 = 0; i4 < 8; i4++) {
        float ha[4][4];
        *(float4*)ha[0] = *(const float4*)(hp + 0);
        *(float4*)ha[1] = *(const float4*)(hp + 256);
        *(float4*)ha[2] = *(const float4*)(hp + 512);
        *(float4*)ha[3] = *(const float4*)(hp + 768);
#pragma unroll
        for (int k = 0; k < 4; k++)
#pragma unroll
            for (int b = 0; b < 4; b++) {
                u64 hh = dup2(ha[b][k]);
                fma2(acc2[0][b], wreg[i4][k][0], hh);
                fma2(acc2[1][b], wreg[i4][k][1], hh);
            }
        hp += 4;
    }
#pragma unroll
    for (int b = 0; b < 4; b++) {
        float x0, x1, x2, x3;
        up2(x0, x1, acc2[0][b]);
        up2(x2, x3, acc2[1][b]);
        *(float4*)(psm + (wid * 4 + b) * 128 + lane * 4) = make_float4(x0, x1, x2, x3);
    }
}

__global__ void __launch_bounds__(256, 1) __cluster_dims__(CLS, 1, 1)
k_main(const float* __restrict__ w_hh, const int* __restrict__ x,
       const float* __restrict__ emb, const float* __restrict__ w_ih,
       const float* __restrict__ bl) {
    extern __shared__ float smem[];

    // ---------------- producer CTAs ----------------
    if (blockIdx.x >= 64) {
        produce_xs((int)blockIdx.x - 64, x, emb, w_ih, bl, smem);
        return;
    }

    // ---------------- LSTM clusters ----------------
    float* wsm  = smem;
    float* psmA = smem + OFF_PSMA;
    float* psmB = smem + OFF_PSMB;
    float* hbas = smem + OFF_HB;
    float* hstA = smem + OFF_HST;
    float* hstB = smem + OFF_HST + 128;

    int tid = threadIdx.x;
    uint32_t rank = ctarank();
    int b0 = (blockIdx.x >> 3) * 8;
    int wid = tid >> 5, lane = tid & 31;

    uint32_t smem_u32 = (uint32_t)__cvta_generic_to_shared(smem);
    uint32_t mbar_u32 = smem_u32 + OFF_MBAR * 4;
    uint32_t hb_u32   = smem_u32 + OFF_HB * 4;

    if (tid == 0) {
        mbar_init(mbar_u32 + 0,  1);
        mbar_init(mbar_u32 + 8,  1);
        mbar_init(mbar_u32 + 16, 1);
        mbar_init(mbar_u32 + 24, 1);
        mbar_expect(mbar_u32 + 0,  PHASE_BYTES);
        mbar_expect(mbar_u32 + 8,  PHASE_BYTES);
        mbar_expect(mbar_u32 + 16, PHASE_BYTES);
        mbar_expect(mbar_u32 + 24, PHASE_BYTES);
    }

    // stage weights
    {
        int jl = tid & 127, dh = tid >> 7;
        int jglob = (jl >> 5) * 256 + 32 * (int)rank + (jl & 31);
        const float* wrow = w_hh + (size_t)jglob * DD;
#pragma unroll 4
        for (int it = 0; it < 32; it++) {
            int d = dh * 128 + it * 4;
            float4 v = *(const float4*)(wrow + d);
            wsm[(d + 0) * 128 + jl] = v.x;
            wsm[(d + 1) * 128 + jl] = v.y;
            wsm[(d + 2) * 128 + jl] = v.z;
            wsm[(d + 3) * 128 + jl] = v.w;
        }
    }
    for (int i = tid; i < 4096; i += 256) hbas[i] = 0.f;
    __syncthreads();

    u64 wreg[8][4][2];
#pragma unroll
    for (int i4 = 0; i4 < 8; i4++)
#pragma unroll
        for (int k = 0; k < 4; k++) {
            const u64* wp2 = (const u64*)(wsm + (wid * 32 + i4 * 4 + k) * 128 + lane * 4);
            wreg[i4][k][0] = wp2[0];
            wreg[i4][k][1] = wp2[1];
        }
    cluster_sync();

    int tl   = tid & 127;
    int half = tid >> 7;
    int actb = tl >> 5;
    int actd = tl & 31;
    float c_reg = 0.f;
    int dglob = 32 * (int)rank + actd;
    int myb  = b0 + half * 4 + actb;

    uint32_t push_rem, poff0, poff1;
    int q0 = tl & 15, q1 = (tl & 15) + 16;
    uint32_t rmb0, rmb1;
    {
        uint32_t tr = (uint32_t)(tl >> 4);
        push_rem = mapa_sh(hb_u32, tr);
        poff0 = (uint32_t)(((q0 >> 3) * 256 + 32 * (int)rank + (q0 & 7) * 4) * 4);
        poff1 = (uint32_t)(((q1 >> 3) * 256 + 32 * (int)rank + (q1 & 7) * 4) * 4);
        rmb0 = mapa_sh(mbar_u32 + (uint32_t)(16 * half) + 0, tr);
        rmb1 = mapa_sh(mbar_u32 + (uint32_t)(16 * half) + 8, tr);
    }
    float* hst = half ? hstB : hstA;

    int phA0 = 0, phA1 = 0, phB0 = 0, phB1 = 0;

    for (int t = 0; t < TT; t++) {
        int bsel = t & 1;
        int nsel = bsel ^ 1;

        // wait for xs producers once per 64-step chunk
        if ((t & 63) == 0) {
            if (tid == 0) {
                const uint32_t* fp = &d_flags[t >> 6];
                while (flag_acquire_ld(fp) < 512u) __nanosleep(256);
            }
            __syncthreads();
        }

        const float* xp = d_xs + ((size_t)myb * TT + t) * GG + dglob;
        float xg0 = xp[0], xg1 = xp[256], xg2 = xp[512], xg3 = xp[768];

        // ================= group A =================
        if (t > 0) {
            if (bsel) { mbar_wait(mbar_u32 + 8, (uint32_t)phA1); phA1 ^= 1; }
            else      { mbar_wait(mbar_u32 + 0, (uint32_t)phA0); phA0 ^= 1; }
            if (tid == 0) mbar_expect(mbar_u32 + (uint32_t)(8 * bsel), PHASE_BYTES);
        }
        lstm_mm(hbas + bsel * 1024, wreg, psmA, wid, lane);
        __syncthreads();

        if (half == 0) {
            float g4[4] = {xg0, xg1, xg2, xg3};
#pragma unroll
            for (int gm = 0; gm < 4; gm++) {
                int jl = gm * 32 + actd;
                float s = 0.f;
#pragma unroll
                for (int ds = 0; ds < 8; ds++)
                    s += psmA[(ds * 4 + actb) * 128 + jl];
                g4[gm] += s;
            }
            float ig = fsig(g4[0]), fg = fsig(g4[1]);
            float gg = ftanhf(g4[2]), og = fsig(g4[3]);
            c_reg = fg * c_reg + ig * gg;
            float hval = og * ftanhf(c_reg);
            d_h[((size_t)myb * TT + t) * DD + dglob] = hval;
            if (t + 1 < TT) {
                hst[actb * 32 + actd] = hval;
                asm volatile("bar.sync 1, 128;" ::: "memory");
                uint32_t dst = push_rem + (uint32_t)(nsel * 4096);
                uint32_t rmb = nsel ? rmb1 : rmb0;
                float4 v0 = *(const float4*)(hst + (q0 >> 3) * 32 + (q0 & 7) * 4);
                float4 v1 = *(const float4*)(hst + (q1 >> 3) * 32 + (q1 & 7) * 4);
                st_async_v4(dst + poff0, v0, rmb);
                st_async_v4(dst + poff1, v1, rmb);
            }
        }

        // ================= group B =================
        if (t > 0) {
            if (bsel) { mbar_wait(mbar_u32 + 24, (uint32_t)phB1); phB1 ^= 1; }
            else      { mbar_wait(mbar_u32 + 16, (uint32_t)phB0); phB0 ^= 1; }
            if (tid == 0) mbar_expect(mbar_u32 + 16 + (uint32_t)(8 * bsel), PHASE_BYTES);
        }
        lstm_mm(hbas + 2048 + bsel * 1024, wreg, psmB, wid, lane);
        __syncthreads();

        if (half == 1) {
            float g4[4] = {xg0, xg1, xg2, xg3};
#pragma unroll
            for (int gm = 0; gm < 4; gm++) {
                int jl = gm * 32 + actd;
                float s = 0.f;
#pragma unroll
                for (int ds = 0; ds < 8; ds++)
                    s += psmB[(ds * 4 + actb) * 128 + jl];
                g4[gm] += s;
            }
            float ig = fsig(g4[0]), fg = fsig(g4[1]);
            float gg = ftanhf(g4[2]), og = fsig(g4[3]);
            c_reg = fg * c_reg + ig * gg;
            float hval = og * ftanhf(c_reg);
            d_h[((size_t)myb * TT + t) * DD + dglob] = hval;
            if (t + 1 < TT) {
                hst[actb * 32 + actd] = hval;
                asm volatile("bar.sync 2, 128;" ::: "memory");
                uint32_t dst = push_rem + (uint32_t)(8192 + nsel * 4096);
                uint32_t rmb = nsel ? rmb1 : rmb0;
                float4 v0 = *(const float4*)(hst + (q0 >> 3) * 32 + (q0 & 7) * 4);
                float4 v1 = *(const float4*)(hst + (q1 >> 3) * 32 + (q1 & 7) * 4);
                st_async_v4(dst + poff0, v0, rmb);
                st_async_v4(dst + poff1, v1, rmb);
            }
        }
    }
}

// ---- correlation m + Y = tanh(m@W_y) + z = Y . w_t  (fused, f32x2) ---------
__global__ void __launch_bounds__(256) k_att(const float* __restrict__ W_y,
                                             const float* __restrict__ w_t) {
    extern __shared__ float sm[];
    float* sdup = sm;
    float* bufT = sm + 512;
    float* mT   = sm + 512 + 9216;
    float* zp   = sm + 512 + 18432;

    int b = blockIdx.x;
    int t0 = blockIdx.y * 32;
    int tid = threadIdx.x;

    float sv0 = d_snorm[b * DD + tid];
    sdup[tid] = sv0;
    sdup[DD + tid] = sv0;

    const float* hrow = d_h + ((size_t)b * TT + t0) * DD + tid;
#pragma unroll 4
    for (int r = 0; r < 32; r++)
        bufT[tid * 36 + r] = hrow[(size_t)r * DD];
    __syncthreads();

    u64 mm2[16];
#pragma unroll
    for (int r2 = 0; r2 < 16; r2++) mm2[r2] = 0ull;
#pragma unroll 2
    for (int d = 0; d < DD; d++) {
        u64 s2 = dup2(sdup[d + tid]);
        const ulonglong2* bp = (const ulonglong2*)(bufT + d * 36);
#pragma unroll
        for (int r4 = 0; r4 < 8; r4++) {
            ulonglong2 v = bp[r4];
            fma2(mm2[2 * r4 + 0], v.x, s2);
            fma2(mm2[2 * r4 + 1], v.y, s2);
        }
    }

    {
        ulonglong2* mtp = (ulonglong2*)(mT + tid * 36);
#pragma unroll
        for (int r4 = 0; r4 < 8; r4++) {
            ulonglong2 v;
            v.x = mm2[2 * r4 + 0];
            v.y = mm2[2 * r4 + 1];
            mtp[r4] = v;
        }
    }
    __syncthreads();

    u64 yy2[16];
#pragma unroll
    for (int r2 = 0; r2 < 16; r2++) yy2[r2] = 0ull;
    for (int d = 0; d < DD; d += 4) {
        float w0 = W_y[(d + 0) * DD + tid];
        float w1 = W_y[(d + 1) * DD + tid];
        float w2 = W_y[(d + 2) * DD + tid];
        float w3 = W_y[(d + 3) * DD + tid];
        u64 wd0 = dup2(w0), wd1 = dup2(w1), wd2 = dup2(w2), wd3 = dup2(w3);
        const ulonglong2* mp0 = (const ulonglong2*)(mT + (d + 0) * 36);
        const ulonglong2* mp1 = (const ulonglong2*)(mT + (d + 1) * 36);
        const ulonglong2* mp2 = (const ulonglong2*)(mT + (d + 2) * 36);
        const ulonglong2* mp3 = (const ulonglong2*)(mT + (d + 3) * 36);
#pragma unroll
        for (int r4 = 0; r4 < 8; r4++) {
            ulonglong2 v0 = mp0[r4], v1 = mp1[r4], v2 = mp2[r4], v3 = mp3[r4];
            fma2(yy2[2 * r4 + 0], v0.x, wd0);
            fma2(yy2[2 * r4 + 1], v0.y, wd0);
            fma2(yy2[2 * r4 + 0], v1.x, wd1);
            fma2(yy2[2 * r4 + 1], v1.y, wd1);
            fma2(yy2[2 * r4 + 0], v2.x, wd2);
            fma2(yy2[2 * r4 + 1], v2.y, wd2);
            fma2(yy2[2 * r4 + 0], v3.x, wd3);
            fma2(yy2[2 * r4 + 1], v3.y, wd3);
        }
    }

    float y[32];
#pragma unroll
    for (int r2 = 0; r2 < 16; r2++) up2(y[2 * r2], y[2 * r2 + 1], yy2[r2]);

    float wt = w_t[tid];
    int lane = tid & 31, wrp = tid >> 5;
#pragma unroll
    for (int r = 0; r < 32; r++) {
        float v = ftanhf(y[r]) * wt;
        v += __shfl_down_sync(0xffffffffu, v, 16);
        v += __shfl_down_sync(0xffffffffu, v, 8);
        v += __shfl_down_sync(0xffffffffu, v, 4);
        v += __shfl_down_sync(0xffffffffu, v, 2);
        v += __shfl_down_sync(0xffffffffu, v, 1);
        if (lane == 0) zp[wrp * 32 + r] = v;
    }
    __syncthreads();
    if (tid < 32) {
        float sacc = 0.f;
#pragma unroll
        for (int w = 0; w < 8; w++) sacc += zp[w * 32 + tid];
        d_z[b * TT + t0 + tid] = sacc;
    }
}

// ---- softmax over T --------------------------------------------------------
__global__ void __launch_bounds__(256) k_soft() {
    int b = blockIdx.x, tid = threadIdx.x;
    __shared__ float zsh[TT];
    __shared__ float red[256];
    zsh[tid] = d_z[b * TT + tid];
    zsh[256 + tid] = d_z[b * TT + 256 + tid];
    __syncthreads();
    float lm = fmaxf(zsh[tid], zsh[tid + 256]);
    red[tid] = lm; __syncthreads();
    for (int s = 128; s > 0; s >>= 1) {
        if (tid < s) red[tid] = fmaxf(red[tid], red[tid + s]);
        __syncthreads();
    }
    float mx = red[0]; __syncthreads();
    float e0 = __expf(zsh[tid] - mx), e1 = __expf(zsh[tid + 256] - mx);
    red[tid] = e0 + e1; __syncthreads();
    for (int s = 128; s > 0; s >>= 1) {
        if (tid < s) red[tid] += red[tid + s];
        __syncthreads();
    }
    float inv = __fdividef(1.f, red[0]);
    d_z[b * TT + tid] = e0 * inv;
    d_z[b * TT + 256 + tid] = e1 * inv;
}

// ---- partial r -------------------------------------------------------------
__global__ void __launch_bounds__(256) k_rpart() {
    int b = blockIdx.x, q = blockIdx.y, tid = threadIdx.x;
    const float* hbp = d_h + ((size_t)b * TT + q * 64) * DD + tid;
    const float* ap  = d_z + b * TT + q * 64;
    float acc = 0.f;
#pragma unroll 8
    for (int t = 0; t < 64; t++)
        acc += ap[t] * hbp[(size_t)t * DD];
    d_rp[(b * 8 + q) * DD + tid] = acc;
}

// ---- final head ------------------------------------------------------------
__global__ void __launch_bounds__(256) k_final(const float* __restrict__ b_f,
                                               float* __restrict__ out) {
    int b = blockIdx.x, tid = threadIdx.x;
    __shared__ float rsh[DD], hls[DD], rrsh[DD], red[256];
    float racc = 0.f;
#pragma unroll
    for (int q = 0; q < 8; q++) racc += d_rp[(b * 8 + q) * DD + tid];
    rsh[tid] = racc;
    hls[tid] = d_h[((size_t)b * TT + (TT - 1)) * DD + tid];
    __syncthreads();
    float acc = 0.f;
    for (int d = 0; d < DD; d++)
        acc += rsh[d] * d_WpT[d * DD + tid] + hls[d] * d_WxT[d * DD + tid];
    rrsh[tid] = ftanhf(acc);
    __syncthreads();
    float lg = b_f[tid];
    for (int e = 0; e < DD; e++) lg += rrsh[e] * d_WfT[e * DD + tid];
    red[tid] = lg; __syncthreads();
    for (int s = 128; s > 0; s >>= 1) {
        if (tid < s) red[tid] = fmaxf(red[tid], red[tid + s]);
        __syncthreads();
    }
    float mx = red[0]; __syncthreads();
    float ex = __expf(lg - mx);
    red[tid] = ex; __syncthreads();
    for (int s = 128; s > 0; s >>= 1) {
        if (tid < s) red[tid] += red[tid + s];
        __syncthreads();
    }
    out[b * DD + tid] = __fdividef(ex, red[0]);
}

// ---------------------------------------------------------------------------
extern "C" void kernel_launch(void* const* d_in, const int* in_sizes, int n_in,
                              void* d_out, int out_size) {
    const int*   x      = (const int*)d_in[0];
    const int*   s      = (const int*)d_in[1];
    const float* emb    = (const float*)d_in[2];
    const float* w_ih   = (const float*)d_in[3];
    const float* w_hh   = (const float*)d_in[4];
    const float* b_lstm = (const float*)d_in[5];
    const float* W_y    = (const float*)d_in[6];
    const float* w_t    = (const float*)d_in[7];
    const float* W_p    = (const float*)d_in[8];
    const float* W_x    = (const float*)d_in[9];
    const float* W_f    = (const float*)d_in[10];
    const float* b_f    = (const float*)d_in[11];
    float* out = (float*)d_out;

    const size_t lstm_smem = LSTM_SMEM_BYTES;
    const size_t att_smem  = (512 + 2 * 256 * 36 + 256) * sizeof(float);
    cudaFuncSetAttribute(k_main, cudaFuncAttributeMaxDynamicSharedMemorySize,
                         (int)lstm_smem);
    cudaFuncSetAttribute(k_att, cudaFuncAttributeMaxDynamicSharedMemorySize,
                         (int)att_smem);

    k_prep<<<256, 256>>>(W_p, W_x, W_f);
    k_snorm<<<1, 256>>>(s, emb);
    k_main<<<144, 256, lstm_smem>>>(w_hh, x, emb, w_ih, b_lstm);
    k_att<<<dim3(64, 16), 256, att_smem>>>(W_y, w_t);
    k_soft<<<64, 256>>>();
    k_rpart<<<dim3(64, 8), 256>>>();
    k_final<<<64, 256>>>(b_f, out);
}

// round 13
// speedup vs baseline: 1.7625x; 1.7625x over previous
#include <cuda_runtime.h>
#include <cstdint>
#include <cstddef>

typedef unsigned long long u64;

#define BB 64
#define TT 512
#define DD 256
#define GG 1024   // 4*D
#define CLS 8     // CTAs per cluster

// ---------------- scratch (device globals; no runtime allocation) ----------
__device__ float d_xs[(size_t)BB * TT * GG];
__device__ float d_h[(size_t)BB * TT * DD];
__device__ float d_snorm[BB * DD];
__device__ float d_WpT[DD * DD];
__device__ float d_WxT[DD * DD];
__device__ float d_WfT[DD * DD];
__device__ float d_z[BB * TT];
__device__ float d_rp[BB * 8 * DD];
__device__ uint32_t d_flags[8];      // per-64-step chunk counters (lstm -> att)

// ---------------- fast activations (MUFU.TANH) -------------------------------
__device__ __forceinline__ float ftanhf(float x) {
    float r; asm("tanh.approx.f32 %0, %1;" : "=f"(r) : "f"(x)); return r;
}
__device__ __forceinline__ float fsig(float x) {
    return fmaf(0.5f, ftanhf(0.5f * x), 0.5f);
}

__device__ __forceinline__ uint32_t ctarank() {
    uint32_t r; asm("mov.u32 %0, %%cluster_ctarank;" : "=r"(r)); return r;
}
__device__ __forceinline__ void cluster_sync() {
    asm volatile("barrier.cluster.arrive.aligned;\n\tbarrier.cluster.wait.aligned;" ::: "memory");
}
__device__ __forceinline__ uint32_t mapa_sh(uint32_t laddr, uint32_t rank) {
    uint32_t ra; asm("mapa.shared::cluster.u32 %0, %1, %2;" : "=r"(ra) : "r"(laddr), "r"(rank));
    return ra;
}
__device__ __forceinline__ void mbar_init(uint32_t addr, uint32_t cnt) {
    asm volatile("mbarrier.init.shared.b64 [%0], %1;" :: "r"(addr), "r"(cnt) : "memory");
}
__device__ __forceinline__ void mbar_expect(uint32_t addr, uint32_t bytes) {
    asm volatile("mbarrier.arrive.expect_tx.shared.b64 _, [%0], %1;"
                 :: "r"(addr), "r"(bytes) : "memory");
}
__device__ __forceinline__ void st_async_v4(uint32_t raddr, float4 v, uint32_t rmbar) {
    asm volatile(
        "st.async.shared::cluster.mbarrier::complete_tx::bytes.v4.b32 "
        "[%0], {%1,%2,%3,%4}, [%5];"
        :: "r"(raddr),
           "r"(__float_as_uint(v.x)), "r"(__float_as_uint(v.y)),
           "r"(__float_as_uint(v.z)), "r"(__float_as_uint(v.w)),
           "r"(rmbar) : "memory");
}
__device__ __forceinline__ void mbar_wait(uint32_t addr, uint32_t parity) {
    asm volatile(
        "{\n\t.reg .pred P;\n\t"
        "WL_%=:\n\t"
        "mbarrier.try_wait.parity.acquire.cluster.shared::cta.b64 P, [%0], %1, 0x989680;\n\t"
        "@!P bra WL_%=;\n\t"
        "}" :: "r"(addr), "r"(parity) : "memory");
}
__device__ __forceinline__ void flag_release_add(uint32_t* p) {
    asm volatile("red.release.gpu.global.add.u32 [%0], %1;" :: "l"(p), "r"(1u) : "memory");
}
__device__ __forceinline__ uint32_t flag_acquire_ld(const uint32_t* p) {
    uint32_t v;
    asm volatile("ld.acquire.gpu.u32 %0, [%1];" : "=r"(v) : "l"(p) : "memory");
    return v;
}

// ---------------- packed f32x2 helpers --------------------------------------
__device__ __forceinline__ u64 dup2(float v) {
    u64 r; asm("mov.b64 %0, {%1, %1};" : "=l"(r) : "f"(v)); return r;
}
__device__ __forceinline__ void fma2(u64& d, u64 a, u64 b) {
    asm("fma.rn.f32x2 %0, %1, %2, %0;" : "+l"(d) : "l"(a), "l"(b));
}
__device__ __forceinline__ void up2(float& lo, float& hi, u64 v) {
    asm("mov.b64 {%0, %1}, %2;" : "=f"(lo), "=f"(hi) : "l"(v));
}

// ---------------- prep (also zeroes chunk flags) -----------------------------
__global__ void k_prep(const float* __restrict__ W_p,
                       const float* __restrict__ W_x, const float* __restrict__ W_f) {
    int i = blockIdx.x * 256 + threadIdx.x;
    if (i < 8) d_flags[i] = 0u;
    if (i < DD * DD) {
        int e = i / DD, d = i % DD;
        d_WpT[d * DD + e] = W_p[i];
        d_WxT[d * DD + e] = W_x[i];
        d_WfT[d * DD + e] = W_f[i];
    }
}

// ---------------- s_norm ----------------------------------------------------
__global__ void k_snorm(const int* __restrict__ s, const float* __restrict__ emb) {
    int d = threadIdx.x;
    float sum = 0.f, sq = 0.f;
    for (int b = 0; b < BB; b++) {
        float v = emb[(size_t)s[b] * DD + d];
        sum += v; sq += v * v;
    }
    float mu  = sum * (1.f / BB);
    float var = sq * (1.f / BB) - mu * mu;
    float inv = rsqrtf(var + 1e-5f);
    for (int b = 0; b < BB; b++) {
        float v = emb[(size_t)s[b] * DD + d];
        d_snorm[b * DD + d] = (v - mu) * inv;
    }
}

// ---------------- xs = emb[x] @ w_ih.T + b  (128x128 tile, f32x2) -----------
__global__ void __launch_bounds__(256) k_xs(const int* __restrict__ x,
                                            const float* __restrict__ emb,
                                            const float* __restrict__ w_ih,
                                            const float* __restrict__ bl) {
    __shared__ float As[16][128];
    __shared__ float Bs[16][128];
    int tid = threadIdx.x;
    int m0 = blockIdx.x * 128, n0 = blockIdx.y * 128;
    int tx = tid & 15, ty = tid >> 4;

    int row_i = tid >> 1, kc = (tid & 1) * 8;
    int tok = x[m0 + row_i];
    const float* arow = emb + (size_t)tok * DD;
    const float* brow = w_ih + (size_t)(n0 + row_i) * DD;

    u64 acc2[8][4];
#pragma unroll
    for (int i = 0; i < 8; i++)
#pragma unroll
        for (int j = 0; j < 4; j++) acc2[i][j] = 0ull;

    for (int k0 = 0; k0 < DD; k0 += 16) {
        float4 a0 = *(const float4*)(arow + k0 + kc);
        float4 a1 = *(const float4*)(arow + k0 + kc + 4);
        float4 b0v = *(const float4*)(brow + k0 + kc);
        float4 b1v = *(const float4*)(brow + k0 + kc + 4);
        As[kc + 0][row_i] = a0.x; As[kc + 1][row_i] = a0.y;
        As[kc + 2][row_i] = a0.z; As[kc + 3][row_i] = a0.w;
        As[kc + 4][row_i] = a1.x; As[kc + 5][row_i] = a1.y;
        As[kc + 6][row_i] = a1.z; As[kc + 7][row_i] = a1.w;
        Bs[kc + 0][row_i] = b0v.x; Bs[kc + 1][row_i] = b0v.y;
        Bs[kc + 2][row_i] = b0v.z; Bs[kc + 3][row_i] = b0v.w;
        Bs[kc + 4][row_i] = b1v.x; Bs[kc + 5][row_i] = b1v.y;
        Bs[kc + 6][row_i] = b1v.z; Bs[kc + 7][row_i] = b1v.w;
        __syncthreads();
#pragma unroll
        for (int k = 0; k < 16; k++) {
            float4 a0v = *(const float4*)&As[k][ty * 8];
            float4 a1v = *(const float4*)&As[k][ty * 8 + 4];
            const u64* bp = (const u64*)&Bs[k][tx * 8];
            u64 bb0 = bp[0], bb1 = bp[1], bb2 = bp[2], bb3 = bp[3];
            float aa[8] = {a0v.x, a0v.y, a0v.z, a0v.w, a1v.x, a1v.y, a1v.z, a1v.w};
#pragma unroll
            for (int i = 0; i < 8; i++) {
                u64 ai = dup2(aa[i]);
                fma2(acc2[i][0], ai, bb0);
                fma2(acc2[i][1], ai, bb1);
                fma2(acc2[i][2], ai, bb2);
                fma2(acc2[i][3], ai, bb3);
            }
        }
        __syncthreads();
    }
    int col = n0 + tx * 8;
    float4 blv0 = *(const float4*)(bl + col);
    float4 blv1 = *(const float4*)(bl + col + 4);
#pragma unroll
    for (int i = 0; i < 8; i++) {
        size_t row = m0 + ty * 8 + i;
        float c0, c1, c2, c3, c4, c5, c6, c7;
        up2(c0, c1, acc2[i][0]);
        up2(c2, c3, acc2[i][1]);
        up2(c4, c5, acc2[i][2]);
        up2(c6, c7, acc2[i][3]);
        float* op = d_xs + row * GG + col;
        *(float4*)op       = make_float4(c0 + blv0.x, c1 + blv0.y, c2 + blv0.z, c3 + blv0.w);
        *(float4*)(op + 4) = make_float4(c4 + blv1.x, c5 + blv1.y, c6 + blv1.z, c7 + blv1.w);
    }
}

// ---------------- att tile (device fn; one 32-t block of one batch) ----------
__device__ void att_tile(int b, int t0, float* sm,
                         const float* __restrict__ W_y,
                         const float* __restrict__ w_t) {
    float* sdup = sm;
    float* bufT = sm + 512;
    float* mT   = sm + 512 + 9216;
    float* zp   = sm + 512 + 18432;
    int tid = threadIdx.x;

    float sv0 = d_snorm[b * DD + tid];
    sdup[tid] = sv0;
    sdup[DD + tid] = sv0;

    const float* hrow = d_h + ((size_t)b * TT + t0) * DD + tid;
#pragma unroll 4
    for (int r = 0; r < 32; r++)
        bufT[tid * 36 + r] = hrow[(size_t)r * DD];
    __syncthreads();

    u64 mm2[16];
#pragma unroll
    for (int r2 = 0; r2 < 16; r2++) mm2[r2] = 0ull;
#pragma unroll 2
    for (int d = 0; d < DD; d++) {
        u64 s2 = dup2(sdup[d + tid]);
        const ulonglong2* bp = (const ulonglong2*)(bufT + d * 36);
#pragma unroll
        for (int r4 = 0; r4 < 8; r4++) {
            ulonglong2 v = bp[r4];
            fma2(mm2[2 * r4 + 0], v.x, s2);
            fma2(mm2[2 * r4 + 1], v.y, s2);
        }
    }

    {
        ulonglong2* mtp = (ulonglong2*)(mT + tid * 36);
#pragma unroll
        for (int r4 = 0; r4 < 8; r4++) {
            ulonglong2 v;
            v.x = mm2[2 * r4 + 0];
            v.y = mm2[2 * r4 + 1];
            mtp[r4] = v;
        }
    }
    __syncthreads();

    u64 yy2[16];
#pragma unroll
    for (int r2 = 0; r2 < 16; r2++) yy2[r2] = 0ull;
    for (int d = 0; d < DD; d += 4) {
        float w0 = W_y[(d + 0) * DD + tid];
        float w1 = W_y[(d + 1) * DD + tid];
        float w2 = W_y[(d + 2) * DD + tid];
        float w3 = W_y[(d + 3) * DD + tid];
        u64 wd0 = dup2(w0), wd1 = dup2(w1), wd2 = dup2(w2), wd3 = dup2(w3);
        const ulonglong2* mp0 = (const ulonglong2*)(mT + (d + 0) * 36);
        const ulonglong2* mp1 = (const ulonglong2*)(mT + (d + 1) * 36);
        const ulonglong2* mp2 = (const ulonglong2*)(mT + (d + 2) * 36);
        const ulonglong2* mp3 = (const ulonglong2*)(mT + (d + 3) * 36);
#pragma unroll
        for (int r4 = 0; r4 < 8; r4++) {
            ulonglong2 v0 = mp0[r4], v1 = mp1[r4], v2 = mp2[r4], v3 = mp3[r4];
            fma2(yy2[2 * r4 + 0], v0.x, wd0);
            fma2(yy2[2 * r4 + 1], v0.y, wd0);
            fma2(yy2[2 * r4 + 0], v1.x, wd1);
            fma2(yy2[2 * r4 + 1], v1.y, wd1);
            fma2(yy2[2 * r4 + 0], v2.x, wd2);
            fma2(yy2[2 * r4 + 1], v2.y, wd2);
            fma2(yy2[2 * r4 + 0], v3.x, wd3);
            fma2(yy2[2 * r4 + 1], v3.y, wd3);
        }
    }

    float y[32];
#pragma unroll
    for (int r2 = 0; r2 < 16; r2++) up2(y[2 * r2], y[2 * r2 + 1], yy2[r2]);

    float wt = w_t[tid];
    int lane = tid & 31, wrp = tid >> 5;
#pragma unroll
    for (int r = 0; r < 32; r++) {
        float v = ftanhf(y[r]) * wt;
        v += __shfl_down_sync(0xffffffffu, v, 16);
        v += __shfl_down_sync(0xffffffffu, v, 8);
        v += __shfl_down_sync(0xffffffffu, v, 4);
        v += __shfl_down_sync(0xffffffffu, v, 2);
        v += __shfl_down_sync(0xffffffffu, v, 1);
        if (lane == 0) zp[wrp * 32 + r] = v;
    }
    __syncthreads();
    if (tid < 32) {
        float sacc = 0.f;
#pragma unroll
        for (int w = 0; w < 8; w++) sacc += zp[w * 32 + tid];
        d_z[b * TT + t0 + tid] = sacc;
    }
    __syncthreads();
}

// ------- main kernel: 8 LSTM clusters (CTA 0..63) + 64 att workers ----------
#define OFF_PSMA  32768
#define OFF_PSMB  (32768 + 4096)
#define OFF_HB    (32768 + 8192)
#define OFF_HST   (OFF_HB + 4096)
#define OFF_MBAR  (OFF_HST + 256)
#define LSTM_SMEM_BYTES ((OFF_MBAR + 8) * 4)
#define PHASE_BYTES 4096u

__device__ __forceinline__ void lstm_mm(const float* hcur,
                                        const u64 (&wreg)[8][4][2],
                                        float* psm, int wid, int lane) {
    u64 acc2[2][4];
#pragma unroll
    for (int b = 0; b < 4; b++) { acc2[0][b] = 0ull; acc2[1][b] = 0ull; }
    const float* hp = hcur + wid * 32;
#pragma unroll
    for (int i4 = 0; i4 < 8; i4++) {
        float ha[4][4];
        *(float4*)ha[0] = *(const float4*)(hp + 0);
        *(float4*)ha[1] = *(const float4*)(hp + 256);
        *(float4*)ha[2] = *(const float4*)(hp + 512);
        *(float4*)ha[3] = *(const float4*)(hp + 768);
#pragma unroll
        for (int k = 0; k < 4; k++)
#pragma unroll
            for (int b = 0; b < 4; b++) {
                u64 hh = dup2(ha[b][k]);
                fma2(acc2[0][b], wreg[i4][k][0], hh);
                fma2(acc2[1][b], wreg[i4][k][1], hh);
            }
        hp += 4;
    }
#pragma unroll
    for (int b = 0; b < 4; b++) {
        float x0, x1, x2, x3;
        up2(x0, x1, acc2[0][b]);
        up2(x2, x3, acc2[1][b]);
        *(float4*)(psm + (wid * 4 + b) * 128 + lane * 4) = make_float4(x0, x1, x2, x3);
    }
}

__global__ void __launch_bounds__(256, 1) __cluster_dims__(CLS, 1, 1)
k_main(const float* __restrict__ w_hh,
       const float* __restrict__ W_y, const float* __restrict__ w_t) {
    extern __shared__ float smem[];

    // ---------------- att worker CTAs (64..127) ----------------
    if (blockIdx.x >= 64) {
        int w = (int)blockIdx.x - 64;
        int tid = threadIdx.x;
        for (int tile = w; tile < 1024; tile += 64) {
            int tb = tile >> 6;         // t-block 0..15 (ordered: early t first)
            int b  = tile & 63;
            int chunk = tb >> 1;
            if (tid == 0) {
                while (flag_acquire_ld(&d_flags[chunk]) < 64u) __nanosleep(128);
            }
            __syncthreads();
            att_tile(b, tb * 32, smem, W_y, w_t);
        }
        return;
    }

    // ---------------- LSTM clusters (CTA 0..63) ----------------
    float* wsm  = smem;
    float* psmA = smem + OFF_PSMA;
    float* psmB = smem + OFF_PSMB;
    float* hbas = smem + OFF_HB;
    float* hstA = smem + OFF_HST;
    float* hstB = smem + OFF_HST + 128;

    int tid = threadIdx.x;
    uint32_t rank = ctarank();
    int b0 = (blockIdx.x >> 3) * 8;
    int wid = tid >> 5, lane = tid & 31;

    uint32_t smem_u32 = (uint32_t)__cvta_generic_to_shared(smem);
    uint32_t mbar_u32 = smem_u32 + OFF_MBAR * 4;
    uint32_t hb_u32   = smem_u32 + OFF_HB * 4;

    if (tid == 0) {
        mbar_init(mbar_u32 + 0,  1);
        mbar_init(mbar_u32 + 8,  1);
        mbar_init(mbar_u32 + 16, 1);
        mbar_init(mbar_u32 + 24, 1);
        mbar_expect(mbar_u32 + 0,  PHASE_BYTES);
        mbar_expect(mbar_u32 + 8,  PHASE_BYTES);
        mbar_expect(mbar_u32 + 16, PHASE_BYTES);
        mbar_expect(mbar_u32 + 24, PHASE_BYTES);
    }

    // stage weights
    {
        int jl = tid & 127, dh = tid >> 7;
        int jglob = (jl >> 5) * 256 + 32 * (int)rank + (jl & 31);
        const float* wrow = w_hh + (size_t)jglob * DD;
#pragma unroll 4
        for (int it = 0; it < 32; it++) {
            int d = dh * 128 + it * 4;
            float4 v = *(const float4*)(wrow + d);
            wsm[(d + 0) * 128 + jl] = v.x;
            wsm[(d + 1) * 128 + jl] = v.y;
            wsm[(d + 2) * 128 + jl] = v.z;
            wsm[(d + 3) * 128 + jl] = v.w;
        }
    }
    for (int i = tid; i < 4096; i += 256) hbas[i] = 0.f;
    __syncthreads();

    u64 wreg[8][4][2];
#pragma unroll
    for (int i4 = 0; i4 < 8; i4++)
#pragma unroll
        for (int k = 0; k < 4; k++) {
            const u64* wp2 = (const u64*)(wsm + (wid * 32 + i4 * 4 + k) * 128 + lane * 4);
            wreg[i4][k][0] = wp2[0];
            wreg[i4][k][1] = wp2[1];
        }
    cluster_sync();

    int tl   = tid & 127;
    int half = tid >> 7;
    int actb = tl >> 5;
    int actd = tl & 31;
    float c_reg = 0.f;
    int dglob = 32 * (int)rank + actd;
    int myb  = b0 + half * 4 + actb;

    uint32_t push_rem, poff0, poff1;
    int q0 = tl & 15, q1 = (tl & 15) + 16;
    uint32_t rmb0, rmb1;
    {
        uint32_t tr = (uint32_t)(tl >> 4);
        push_rem = mapa_sh(hb_u32, tr);
        poff0 = (uint32_t)(((q0 >> 3) * 256 + 32 * (int)rank + (q0 & 7) * 4) * 4);
        poff1 = (uint32_t)(((q1 >> 3) * 256 + 32 * (int)rank + (q1 & 7) * 4) * 4);
        rmb0 = mapa_sh(mbar_u32 + (uint32_t)(16 * half) + 0, tr);
        rmb1 = mapa_sh(mbar_u32 + (uint32_t)(16 * half) + 8, tr);
    }
    float* hst = half ? hstB : hstA;

    int phA0 = 0, phA1 = 0, phB0 = 0, phB1 = 0;

    for (int t = 0; t < TT; t++) {
        int bsel = t & 1;
        int nsel = bsel ^ 1;

        const float* xp = d_xs + ((size_t)myb * TT + t) * GG + dglob;
        float xg0 = xp[0], xg1 = xp[256], xg2 = xp[512], xg3 = xp[768];

        // ================= group A =================
        if (t > 0) {
            if (bsel) { mbar_wait(mbar_u32 + 8, (uint32_t)phA1); phA1 ^= 1; }
            else      { mbar_wait(mbar_u32 + 0, (uint32_t)phA0); phA0 ^= 1; }
            if (tid == 0) mbar_expect(mbar_u32 + (uint32_t)(8 * bsel), PHASE_BYTES);
        }
        lstm_mm(hbas + bsel * 1024, wreg, psmA, wid, lane);
        __syncthreads();

        if (half == 0) {
            float g4[4] = {xg0, xg1, xg2, xg3};
#pragma unroll
            for (int gm = 0; gm < 4; gm++) {
                int jl = gm * 32 + actd;
                float s = 0.f;
#pragma unroll
                for (int ds = 0; ds < 8; ds++)
                    s += psmA[(ds * 4 + actb) * 128 + jl];
                g4[gm] += s;
            }
            float ig = fsig(g4[0]), fg = fsig(g4[1]);
            float gg = ftanhf(g4[2]), og = fsig(g4[3]);
            c_reg = fg * c_reg + ig * gg;
            float hval = og * ftanhf(c_reg);
            d_h[((size_t)myb * TT + t) * DD + dglob] = hval;
            if (t + 1 < TT) {
                hst[actb * 32 + actd] = hval;
                asm volatile("bar.sync 1, 128;" ::: "memory");
                uint32_t dst = push_rem + (uint32_t)(nsel * 4096);
                uint32_t rmb = nsel ? rmb1 : rmb0;
                float4 v0 = *(const float4*)(hst + (q0 >> 3) * 32 + (q0 & 7) * 4);
                float4 v1 = *(const float4*)(hst + (q1 >> 3) * 32 + (q1 & 7) * 4);
                st_async_v4(dst + poff0, v0, rmb);
                st_async_v4(dst + poff1, v1, rmb);
            }
        }

        // ================= group B =================
        if (t > 0) {
            if (bsel) { mbar_wait(mbar_u32 + 24, (uint32_t)phB1); phB1 ^= 1; }
            else      { mbar_wait(mbar_u32 + 16, (uint32_t)phB0); phB0 ^= 1; }
            if (tid == 0) mbar_expect(mbar_u32 + 16 + (uint32_t)(8 * bsel), PHASE_BYTES);
        }
        lstm_mm(hbas + 2048 + bsel * 1024, wreg, psmB, wid, lane);
        __syncthreads();

        if (half == 1) {
            float g4[4] = {xg0, xg1, xg2, xg3};
#pragma unroll
            for (int gm = 0; gm < 4; gm++) {
                int jl = gm * 32 + actd;
                float s = 0.f;
#pragma unroll
                for (int ds = 0; ds < 8; ds++)
                    s += psmB[(ds * 4 + actb) * 128 + jl];
                g4[gm] += s;
            }
            float ig = fsig(g4[0]), fg = fsig(g4[1]);
            float gg = ftanhf(g4[2]), og = fsig(g4[3]);
            c_reg = fg * c_reg + ig * gg;
            float hval = og * ftanhf(c_reg);
            d_h[((size_t)myb * TT + t) * DD + dglob] = hval;
            if (t + 1 < TT) {
                hst[actb * 32 + actd] = hval;
                asm volatile("bar.sync 2, 128;" ::: "memory");
                uint32_t dst = push_rem + (uint32_t)(8192 + nsel * 4096);
                uint32_t rmb = nsel ? rmb1 : rmb0;
                float4 v0 = *(const float4*)(hst + (q0 >> 3) * 32 + (q0 & 7) * 4);
                float4 v1 = *(const float4*)(hst + (q1 >> 3) * 32 + (q1 & 7) * 4);
                st_async_v4(dst + poff0, v0, rmb);
                st_async_v4(dst + poff1, v1, rmb);
            }
        }

        // ---- publish chunk completion to att workers -----------------------
        if ((t & 63) == 63) {
            __syncthreads();
            if (tid == 0) {
                asm volatile("fence.acq_rel.gpu;" ::: "memory");
                flag_release_add(&d_flags[t >> 6]);
            }
        }
    }
}

// ---- softmax over T --------------------------------------------------------
__global__ void __launch_bounds__(256) k_soft() {
    int b = blockIdx.x, tid = threadIdx.x;
    __shared__ float zsh[TT];
    __shared__ float red[256];
    zsh[tid] = d_z[b * TT + tid];
    zsh[256 + tid] = d_z[b * TT + 256 + tid];
    __syncthreads();
    float lm = fmaxf(zsh[tid], zsh[tid + 256]);
    red[tid] = lm; __syncthreads();
    for (int s = 128; s > 0; s >>= 1) {
        if (tid < s) red[tid] = fmaxf(red[tid], red[tid + s]);
        __syncthreads();
    }
    float mx = red[0]; __syncthreads();
    float e0 = __expf(zsh[tid] - mx), e1 = __expf(zsh[tid + 256] - mx);
    red[tid] = e0 + e1; __syncthreads();
    for (int s = 128; s > 0; s >>= 1) {
        if (tid < s) red[tid] += red[tid + s];
        __syncthreads();
    }
    float inv = __fdividef(1.f, red[0]);
    d_z[b * TT + tid] = e0 * inv;
    d_z[b * TT + 256 + tid] = e1 * inv;
}

// ---- partial r -------------------------------------------------------------
__global__ void __launch_bounds__(256) k_rpart() {
    int b = blockIdx.x, q = blockIdx.y, tid = threadIdx.x;
    const float* hbp = d_h + ((size_t)b * TT + q * 64) * DD + tid;
    const float* ap  = d_z + b * TT + q * 64;
    float acc = 0.f;
#pragma unroll 8
    for (int t = 0; t < 64; t++)
        acc += ap[t] * hbp[(size_t)t * DD];
    d_rp[(b * 8 + q) * DD + tid] = acc;
}

// ---- final head ------------------------------------------------------------
__global__ void __launch_bounds__(256) k_final(const float* __restrict__ b_f,
                                               float* __restrict__ out) {
    int b = blockIdx.x, tid = threadIdx.x;
    __shared__ float rsh[DD], hls[DD], rrsh[DD], red[256];
    float racc = 0.f;
#pragma unroll
    for (int q = 0; q < 8; q++) racc += d_rp[(b * 8 + q) * DD + tid];
    rsh[tid] = racc;
    hls[tid] = d_h[((size_t)b * TT + (TT - 1)) * DD + tid];
    __syncthreads();
    float acc = 0.f;
    for (int d = 0; d < DD; d++)
        acc += rsh[d] * d_WpT[d * DD + tid] + hls[d] * d_WxT[d * DD + tid];
    rrsh[tid] = ftanhf(acc);
    __syncthreads();
    float lg = b_f[tid];
    for (int e = 0; e < DD; e++) lg += rrsh[e] * d_WfT[e * DD + tid];
    red[tid] = lg; __syncthreads();
    for (int s = 128; s > 0; s >>= 1) {
        if (tid < s) red[tid] = fmaxf(red[tid], red[tid + s]);
        __syncthreads();
    }
    float mx = red[0]; __syncthreads();
    float ex = __expf(lg - mx);
    red[tid] = ex; __syncthreads();
    for (int s = 128; s > 0; s >>= 1) {
        if (tid < s) red[tid] += red[tid + s];
        __syncthreads();
    }
    out[b * DD + tid] = __fdividef(ex, red[0]);
}

// ---------------------------------------------------------------------------
extern "C" void kernel_launch(void* const* d_in, const int* in_sizes, int n_in,
                              void* d_out, int out_size) {
    const int*   x      = (const int*)d_in[0];
    const int*   s      = (const int*)d_in[1];
    const float* emb    = (const float*)d_in[2];
    const float* w_ih   = (const float*)d_in[3];
    const float* w_hh   = (const float*)d_in[4];
    const float* b_lstm = (const float*)d_in[5];
    const float* W_y    = (const float*)d_in[6];
    const float* w_t    = (const float*)d_in[7];
    const float* W_p    = (const float*)d_in[8];
    const float* W_x    = (const float*)d_in[9];
    const float* W_f    = (const float*)d_in[10];
    const float* b_f    = (const float*)d_in[11];
    float* out = (float*)d_out;

    const size_t lstm_smem = LSTM_SMEM_BYTES;
    cudaFuncSetAttribute(k_main, cudaFuncAttributeMaxDynamicSharedMemorySize,
                         (int)lstm_smem);

    k_prep<<<256, 256>>>(W_p, W_x, W_f);
    k_snorm<<<1, 256>>>(s, emb);
    k_xs<<<dim3(256, 8), 256>>>(x, emb, w_ih, b_lstm);
    k_main<<<128, 256, lstm_smem>>>(w_hh, W_y, w_t);
    k_soft<<<64, 256>>>();
    k_rpart<<<dim3(64, 8), 256>>>();
    k_final<<<64, 256>>>(b_f, out);
}

// round 14
// speedup vs baseline: 2.2077x; 1.2526x over previous
#include <cuda_runtime.h>
#include <cstdint>
#include <cstddef>

typedef unsigned long long u64;

#define BB 64
#define TT 512
#define DD 256
#define GG 1024   // 4*D
#define CLS 8     // CTAs per cluster

// ---------------- scratch (device globals; no runtime allocation) ----------
__device__ float d_xs[(size_t)BB * TT * GG];
__device__ float d_h[(size_t)BB * TT * DD];
__device__ float d_snorm[BB * DD];
__device__ float d_WpT[DD * DD];
__device__ float d_WxT[DD * DD];
__device__ float d_WfT[DD * DD];
__device__ float d_z[BB * TT];

// ---------------- fast activations (MUFU.TANH) -------------------------------
__device__ __forceinline__ float ftanhf(float x) {
    float r; asm("tanh.approx.f32 %0, %1;" : "=f"(r) : "f"(x)); return r;
}
__device__ __forceinline__ float fsig(float x) {
    return fmaf(0.5f, ftanhf(0.5f * x), 0.5f);
}

__device__ __forceinline__ uint32_t ctarank() {
    uint32_t r; asm("mov.u32 %0, %%cluster_ctarank;" : "=r"(r)); return r;
}
__device__ __forceinline__ void cluster_sync() {
    asm volatile("barrier.cluster.arrive.aligned;\n\tbarrier.cluster.wait.aligned;" ::: "memory");
}
__device__ __forceinline__ uint32_t mapa_sh(uint32_t laddr, uint32_t rank) {
    uint32_t ra; asm("mapa.shared::cluster.u32 %0, %1, %2;" : "=r"(ra) : "r"(laddr), "r"(rank));
    return ra;
}
__device__ __forceinline__ void mbar_init(uint32_t addr, uint32_t cnt) {
    asm volatile("mbarrier.init.shared.b64 [%0], %1;" :: "r"(addr), "r"(cnt) : "memory");
}
__device__ __forceinline__ void mbar_expect(uint32_t addr, uint32_t bytes) {
    asm volatile("mbarrier.arrive.expect_tx.shared.b64 _, [%0], %1;"
                 :: "r"(addr), "r"(bytes) : "memory");
}
__device__ __forceinline__ void st_async_v4(uint32_t raddr, float4 v, uint32_t rmbar) {
    asm volatile(
        "st.async.shared::cluster.mbarrier::complete_tx::bytes.v4.b32 "
        "[%0], {%1,%2,%3,%4}, [%5];"
        :: "r"(raddr),
           "r"(__float_as_uint(v.x)), "r"(__float_as_uint(v.y)),
           "r"(__float_as_uint(v.z)), "r"(__float_as_uint(v.w)),
           "r"(rmbar) : "memory");
}
__device__ __forceinline__ void mbar_wait(uint32_t addr, uint32_t parity) {
    asm volatile(
        "{\n\t.reg .pred P;\n\t"
        "WL_%=:\n\t"
        "mbarrier.try_wait.parity.acquire.cluster.shared::cta.b64 P, [%0], %1, 0x989680;\n\t"
        "@!P bra WL_%=;\n\t"
        "}" :: "r"(addr), "r"(parity) : "memory");
}

// ---------------- packed f32x2 helpers --------------------------------------
__device__ __forceinline__ u64 dup2(float v) {
    u64 r; asm("mov.b64 %0, {%1, %1};" : "=l"(r) : "f"(v)); return r;
}
__device__ __forceinline__ void fma2(u64& d, u64 a, u64 b) {
    asm("fma.rn.f32x2 %0, %1, %2, %0;" : "+l"(d) : "l"(a), "l"(b));
}
__device__ __forceinline__ void up2(float& lo, float& hi, u64 v) {
    asm("mov.b64 {%0, %1}, %2;" : "=f"(lo), "=f"(hi) : "l"(v));
}

// ---------------- prep ------------------------------------------------------
__global__ void k_prep(const float* __restrict__ W_p,
                       const float* __restrict__ W_x, const float* __restrict__ W_f) {
    int i = blockIdx.x * 256 + threadIdx.x;
    if (i < DD * DD) {
        int e = i / DD, d = i % DD;
        d_WpT[d * DD + e] = W_p[i];
        d_WxT[d * DD + e] = W_x[i];
        d_WfT[d * DD + e] = W_f[i];
    }
}

// ---------------- s_norm ----------------------------------------------------
__global__ void k_snorm(const int* __restrict__ s, const float* __restrict__ emb) {
    int d = threadIdx.x;
    float sum = 0.f, sq = 0.f;
    for (int b = 0; b < BB; b++) {
        float v = emb[(size_t)s[b] * DD + d];
        sum += v; sq += v * v;
    }
    float mu  = sum * (1.f / BB);
    float var = sq * (1.f / BB) - mu * mu;
    float inv = rsqrtf(var + 1e-5f);
    for (int b = 0; b < BB; b++) {
        float v = emb[(size_t)s[b] * DD + d];
        d_snorm[b * DD + d] = (v - mu) * inv;
    }
}

// ---------------- xs = emb[x] @ w_ih.T + b  (128x128 tile, f32x2) -----------
__global__ void __launch_bounds__(256) k_xs(const int* __restrict__ x,
                                            const float* __restrict__ emb,
                                            const float* __restrict__ w_ih,
                                            const float* __restrict__ bl) {
    __shared__ float As[16][128];
    __shared__ float Bs[16][128];
    int tid = threadIdx.x;
    int m0 = blockIdx.x * 128, n0 = blockIdx.y * 128;
    int tx = tid & 15, ty = tid >> 4;

    int row_i = tid >> 1, kc = (tid & 1) * 8;
    int tok = x[m0 + row_i];
    const float* arow = emb + (size_t)tok * DD;
    const float* brow = w_ih + (size_t)(n0 + row_i) * DD;

    u64 acc2[8][4];
#pragma unroll
    for (int i = 0; i < 8; i++)
#pragma unroll
        for (int j = 0; j < 4; j++) acc2[i][j] = 0ull;

    for (int k0 = 0; k0 < DD; k0 += 16) {
        float4 a0 = *(const float4*)(arow + k0 + kc);
        float4 a1 = *(const float4*)(arow + k0 + kc + 4);
        float4 b0v = *(const float4*)(brow + k0 + kc);
        float4 b1v = *(const float4*)(brow + k0 + kc + 4);
        As[kc + 0][row_i] = a0.x; As[kc + 1][row_i] = a0.y;
        As[kc + 2][row_i] = a0.z; As[kc + 3][row_i] = a0.w;
        As[kc + 4][row_i] = a1.x; As[kc + 5][row_i] = a1.y;
        As[kc + 6][row_i] = a1.z; As[kc + 7][row_i] = a1.w;
        Bs[kc + 0][row_i] = b0v.x; Bs[kc + 1][row_i] = b0v.y;
        Bs[kc + 2][row_i] = b0v.z; Bs[kc + 3][row_i] = b0v.w;
        Bs[kc + 4][row_i] = b1v.x; Bs[kc + 5][row_i] = b1v.y;
        Bs[kc + 6][row_i] = b1v.z; Bs[kc + 7][row_i] = b1v.w;
        __syncthreads();
#pragma unroll
        for (int k = 0; k < 16; k++) {
            float4 a0v = *(const float4*)&As[k][ty * 8];
            float4 a1v = *(const float4*)&As[k][ty * 8 + 4];
            const ulonglong2* bp2 = (const ulonglong2*)&Bs[k][tx * 8];
            ulonglong2 bA = bp2[0], bB = bp2[1];
            float aa[8] = {a0v.x, a0v.y, a0v.z, a0v.w, a1v.x, a1v.y, a1v.z, a1v.w};
#pragma unroll
            for (int i = 0; i < 8; i++) {
                u64 ai = dup2(aa[i]);
                fma2(acc2[i][0], ai, bA.x);
                fma2(acc2[i][1], ai, bA.y);
                fma2(acc2[i][2], ai, bB.x);
                fma2(acc2[i][3], ai, bB.y);
            }
        }
        __syncthreads();
    }
    int col = n0 + tx * 8;
    float4 blv0 = *(const float4*)(bl + col);
    float4 blv1 = *(const float4*)(bl + col + 4);
#pragma unroll
    for (int i = 0; i < 8; i++) {
        size_t row = m0 + ty * 8 + i;
        float c0, c1, c2, c3, c4, c5, c6, c7;
        up2(c0, c1, acc2[i][0]);
        up2(c2, c3, acc2[i][1]);
        up2(c4, c5, acc2[i][2]);
        up2(c6, c7, acc2[i][3]);
        float* op = d_xs + row * GG + col;
        *(float4*)op       = make_float4(c0 + blv0.x, c1 + blv0.y, c2 + blv0.z, c3 + blv0.w);
        *(float4*)(op + 4) = make_float4(c4 + blv1.x, c5 + blv1.y, c6 + blv1.z, c7 + blv1.w);
    }
}

// ---------------- LSTM recurrence: R11 config (proven) -----------------------
#define OFF_PSMA  32768
#define OFF_PSMB  (32768 + 4096)
#define OFF_HB    (32768 + 8192)
#define OFF_HST   (OFF_HB + 4096)
#define OFF_MBAR  (OFF_HST + 256)
#define LSTM_SMEM_BYTES ((OFF_MBAR + 8) * 4)
#define PHASE_BYTES 4096u

__device__ __forceinline__ void lstm_mm(const float* hcur,
                                        const u64 (&wreg)[8][4][2],
                                        float* psm, int wid, int lane) {
    u64 acc2[2][4];
#pragma unroll
    for (int b = 0; b < 4; b++) { acc2[0][b] = 0ull; acc2[1][b] = 0ull; }
    const float* hp = hcur + wid * 32;
#pragma unroll
    for (int i4 = 0; i4 < 8; i4++) {
        float ha[4][4];
        *(float4*)ha[0] = *(const float4*)(hp + 0);
        *(float4*)ha[1] = *(const float4*)(hp + 256);
        *(float4*)ha[2] = *(const float4*)(hp + 512);
        *(float4*)ha[3] = *(const float4*)(hp + 768);
#pragma unroll
        for (int k = 0; k < 4; k++)
#pragma unroll
            for (int b = 0; b < 4; b++) {
                u64 hh = dup2(ha[b][k]);
                fma2(acc2[0][b], wreg[i4][k][0], hh);
                fma2(acc2[1][b], wreg[i4][k][1], hh);
            }
        hp += 4;
    }
#pragma unroll
    for (int b = 0; b < 4; b++) {
        float x0, x1, x2, x3;
        up2(x0, x1, acc2[0][b]);
        up2(x2, x3, acc2[1][b]);
        *(float4*)(psm + (wid * 4 + b) * 128 + lane * 4) = make_float4(x0, x1, x2, x3);
    }
}

__global__ void __launch_bounds__(256, 1) __cluster_dims__(CLS, 1, 1)
k_lstm2(const float* __restrict__ w_hh) {
    extern __shared__ float smem[];
    float* wsm  = smem;
    float* psmA = smem + OFF_PSMA;
    float* psmB = smem + OFF_PSMB;
    float* hbas = smem + OFF_HB;
    float* hstA = smem + OFF_HST;
    float* hstB = smem + OFF_HST + 128;

    int tid = threadIdx.x;
    uint32_t rank = ctarank();
    int b0 = (blockIdx.x >> 3) * 8;
    int wid = tid >> 5, lane = tid & 31;

    uint32_t smem_u32 = (uint32_t)__cvta_generic_to_shared(smem);
    uint32_t mbar_u32 = smem_u32 + OFF_MBAR * 4;
    uint32_t hb_u32   = smem_u32 + OFF_HB * 4;

    if (tid == 0) {
        mbar_init(mbar_u32 + 0,  1);
        mbar_init(mbar_u32 + 8,  1);
        mbar_init(mbar_u32 + 16, 1);
        mbar_init(mbar_u32 + 24, 1);
        mbar_expect(mbar_u32 + 0,  PHASE_BYTES);
        mbar_expect(mbar_u32 + 8,  PHASE_BYTES);
        mbar_expect(mbar_u32 + 16, PHASE_BYTES);
        mbar_expect(mbar_u32 + 24, PHASE_BYTES);
    }

    // stage weights
    {
        int jl = tid & 127, dh = tid >> 7;
        int jglob = (jl >> 5) * 256 + 32 * (int)rank + (jl & 31);
        const float* wrow = w_hh + (size_t)jglob * DD;
#pragma unroll 4
        for (int it = 0; it < 32; it++) {
            int d = dh * 128 + it * 4;
            float4 v = *(const float4*)(wrow + d);
            wsm[(d + 0) * 128 + jl] = v.x;
            wsm[(d + 1) * 128 + jl] = v.y;
            wsm[(d + 2) * 128 + jl] = v.z;
            wsm[(d + 3) * 128 + jl] = v.w;
        }
    }
    for (int i = tid; i < 4096; i += 256) hbas[i] = 0.f;
    __syncthreads();

    u64 wreg[8][4][2];
#pragma unroll
    for (int i4 = 0; i4 < 8; i4++)
#pragma unroll
        for (int k = 0; k < 4; k++) {
            const u64* wp2 = (const u64*)(wsm + (wid * 32 + i4 * 4 + k) * 128 + lane * 4);
            wreg[i4][k][0] = wp2[0];
            wreg[i4][k][1] = wp2[1];
        }
    cluster_sync();

    int tl   = tid & 127;
    int half = tid >> 7;
    int actb = tl >> 5;
    int actd = tl & 31;
    float c_reg = 0.f;
    int dglob = 32 * (int)rank + actd;
    int myb  = b0 + half * 4 + actb;

    uint32_t push_rem, poff0, poff1;
    int q0 = tl & 15, q1 = (tl & 15) + 16;
    uint32_t rmb0, rmb1;
    {
        uint32_t tr = (uint32_t)(tl >> 4);
        push_rem = mapa_sh(hb_u32, tr);
        poff0 = (uint32_t)(((q0 >> 3) * 256 + 32 * (int)rank + (q0 & 7) * 4) * 4);
        poff1 = (uint32_t)(((q1 >> 3) * 256 + 32 * (int)rank + (q1 & 7) * 4) * 4);
        rmb0 = mapa_sh(mbar_u32 + (uint32_t)(16 * half) + 0, tr);
        rmb1 = mapa_sh(mbar_u32 + (uint32_t)(16 * half) + 8, tr);
    }
    float* hst = half ? hstB : hstA;

    int phA0 = 0, phA1 = 0, phB0 = 0, phB1 = 0;

    for (int t = 0; t < TT; t++) {
        int bsel = t & 1;
        int nsel = bsel ^ 1;

        const float* xp = d_xs + ((size_t)myb * TT + t) * GG + dglob;
        float xg0 = xp[0], xg1 = xp[256], xg2 = xp[512], xg3 = xp[768];

        // ================= group A =================
        if (t > 0) {
            if (bsel) { mbar_wait(mbar_u32 + 8, (uint32_t)phA1); phA1 ^= 1; }
            else      { mbar_wait(mbar_u32 + 0, (uint32_t)phA0); phA0 ^= 1; }
            if (tid == 0) mbar_expect(mbar_u32 + (uint32_t)(8 * bsel), PHASE_BYTES);
        }
        lstm_mm(hbas + bsel * 1024, wreg, psmA, wid, lane);
        __syncthreads();

        if (half == 0) {
            float g4[4] = {xg0, xg1, xg2, xg3};
#pragma unroll
            for (int gm = 0; gm < 4; gm++) {
                int jl = gm * 32 + actd;
                float s = 0.f;
#pragma unroll
                for (int ds = 0; ds < 8; ds++)
                    s += psmA[(ds * 4 + actb) * 128 + jl];
                g4[gm] += s;
            }
            float ig = fsig(g4[0]), fg = fsig(g4[1]);
            float gg = ftanhf(g4[2]), og = fsig(g4[3]);
            c_reg = fg * c_reg + ig * gg;
            float hval = og * ftanhf(c_reg);
            d_h[((size_t)myb * TT + t) * DD + dglob] = hval;
            if (t + 1 < TT) {
                hst[actb * 32 + actd] = hval;
                asm volatile("bar.sync 1, 128;" ::: "memory");
                uint32_t dst = push_rem + (uint32_t)(nsel * 4096);
                uint32_t rmb = nsel ? rmb1 : rmb0;
                float4 v0 = *(const float4*)(hst + (q0 >> 3) * 32 + (q0 & 7) * 4);
                float4 v1 = *(const float4*)(hst + (q1 >> 3) * 32 + (q1 & 7) * 4);
                st_async_v4(dst + poff0, v0, rmb);
                st_async_v4(dst + poff1, v1, rmb);
            }
        }

        // ================= group B =================
        if (t > 0) {
            if (bsel) { mbar_wait(mbar_u32 + 24, (uint32_t)phB1); phB1 ^= 1; }
            else      { mbar_wait(mbar_u32 + 16, (uint32_t)phB0); phB0 ^= 1; }
            if (tid == 0) mbar_expect(mbar_u32 + 16 + (uint32_t)(8 * bsel), PHASE_BYTES);
        }
        lstm_mm(hbas + 2048 + bsel * 1024, wreg, psmB, wid, lane);
        __syncthreads();

        if (half == 1) {
            float g4[4] = {xg0, xg1, xg2, xg3};
#pragma unroll
            for (int gm = 0; gm < 4; gm++) {
                int jl = gm * 32 + actd;
                float s = 0.f;
#pragma unroll
                for (int ds = 0; ds < 8; ds++)
                    s += psmB[(ds * 4 + actb) * 128 + jl];
                g4[gm] += s;
            }
            float ig = fsig(g4[0]), fg = fsig(g4[1]);
            float gg = ftanhf(g4[2]), og = fsig(g4[3]);
            c_reg = fg * c_reg + ig * gg;
            float hval = og * ftanhf(c_reg);
            d_h[((size_t)myb * TT + t) * DD + dglob] = hval;
            if (t + 1 < TT) {
                hst[actb * 32 + actd] = hval;
                asm volatile("bar.sync 2, 128;" ::: "memory");
                uint32_t dst = push_rem + (uint32_t)(8192 + nsel * 4096);
                uint32_t rmb = nsel ? rmb1 : rmb0;
                float4 v0 = *(const float4*)(hst + (q0 >> 3) * 32 + (q0 & 7) * 4);
                float4 v1 = *(const float4*)(hst + (q1 >> 3) * 32 + (q1 & 7) * 4);
                st_async_v4(dst + poff0, v0, rmb);
                st_async_v4(dst + poff1, v1, rmb);
            }
        }
    }
}

// ---- correlation m + Y = tanh(m@W_y) + z = Y . w_t  (fused, f32x2) ---------
__global__ void __launch_bounds__(256) k_att(const float* __restrict__ W_y,
                                             const float* __restrict__ w_t) {
    extern __shared__ float sm[];
    float* sdup = sm;
    float* bufT = sm + 512;
    float* mT   = sm + 512 + 9216;
    float* zp   = sm + 512 + 18432;

    int b = blockIdx.x;
    int t0 = blockIdx.y * 32;
    int tid = threadIdx.x;

    float sv0 = d_snorm[b * DD + tid];
    sdup[tid] = sv0;
    sdup[DD + tid] = sv0;

    const float* hrow = d_h + ((size_t)b * TT + t0) * DD + tid;
#pragma unroll 4
    for (int r = 0; r < 32; r++)
        bufT[tid * 36 + r] = hrow[(size_t)r * DD];
    __syncthreads();

    u64 mm2[16];
#pragma unroll
    for (int r2 = 0; r2 < 16; r2++) mm2[r2] = 0ull;
#pragma unroll 2
    for (int d = 0; d < DD; d++) {
        u64 s2 = dup2(sdup[d + tid]);
        const ulonglong2* bp = (const ulonglong2*)(bufT + d * 36);
#pragma unroll
        for (int r4 = 0; r4 < 8; r4++) {
            ulonglong2 v = bp[r4];
            fma2(mm2[2 * r4 + 0], v.x, s2);
            fma2(mm2[2 * r4 + 1], v.y, s2);
        }
    }

    {
        ulonglong2* mtp = (ulonglong2*)(mT + tid * 36);
#pragma unroll
        for (int r4 = 0; r4 < 8; r4++) {
            ulonglong2 v;
            v.x = mm2[2 * r4 + 0];
            v.y = mm2[2 * r4 + 1];
            mtp[r4] = v;
        }
    }
    __syncthreads();

    u64 yy2[16];
#pragma unroll
    for (int r2 = 0; r2 < 16; r2++) yy2[r2] = 0ull;
    for (int d = 0; d < DD; d += 4) {
        float w0 = W_y[(d + 0) * DD + tid];
        float w1 = W_y[(d + 1) * DD + tid];
        float w2 = W_y[(d + 2) * DD + tid];
        float w3 = W_y[(d + 3) * DD + tid];
        u64 wd0 = dup2(w0), wd1 = dup2(w1), wd2 = dup2(w2), wd3 = dup2(w3);
        const ulonglong2* mp0 = (const ulonglong2*)(mT + (d + 0) * 36);
        const ulonglong2* mp1 = (const ulonglong2*)(mT + (d + 1) * 36);
        const ulonglong2* mp2 = (const ulonglong2*)(mT + (d + 2) * 36);
        const ulonglong2* mp3 = (const ulonglong2*)(mT + (d + 3) * 36);
#pragma unroll
        for (int r4 = 0; r4 < 8; r4++) {
            ulonglong2 v0 = mp0[r4], v1 = mp1[r4], v2 = mp2[r4], v3 = mp3[r4];
            fma2(yy2[2 * r4 + 0], v0.x, wd0);
            fma2(yy2[2 * r4 + 1], v0.y, wd0);
            fma2(yy2[2 * r4 + 0], v1.x, wd1);
            fma2(yy2[2 * r4 + 1], v1.y, wd1);
            fma2(yy2[2 * r4 + 0], v2.x, wd2);
            fma2(yy2[2 * r4 + 1], v2.y, wd2);
            fma2(yy2[2 * r4 + 0], v3.x, wd3);
            fma2(yy2[2 * r4 + 1], v3.y, wd3);
        }
    }

    float y[32];
#pragma unroll
    for (int r2 = 0; r2 < 16; r2++) up2(y[2 * r2], y[2 * r2 + 1], yy2[r2]);

    float wt = w_t[tid];
    int lane = tid & 31, wrp = tid >> 5;
#pragma unroll
    for (int r = 0; r < 32; r++) {
        float v = ftanhf(y[r]) * wt;
        v += __shfl_down_sync(0xffffffffu, v, 16);
        v += __shfl_down_sync(0xffffffffu, v, 8);
        v += __shfl_down_sync(0xffffffffu, v, 4);
        v += __shfl_down_sync(0xffffffffu, v, 2);
        v += __shfl_down_sync(0xffffffffu, v, 1);
        if (lane == 0) zp[wrp * 32 + r] = v;
    }
    __syncthreads();
    if (tid < 32) {
        float sacc = 0.f;
#pragma unroll
        for (int w = 0; w < 8; w++) sacc += zp[w * 32 + tid];
        d_z[b * TT + t0 + tid] = sacc;
    }
}

// ---- fused head: softmax(z) -> r = sum a*h -> final MLP + softmax ----------
__global__ void __launch_bounds__(256) k_head(const float* __restrict__ b_f,
                                              float* __restrict__ out) {
    int b = blockIdx.x, tid = threadIdx.x;
    __shared__ float zsh[TT];
    __shared__ float red[256];
    __shared__ float rsh[DD], hls[DD], rrsh[DD];

    // softmax over T (in-place on zsh)
    zsh[tid] = d_z[b * TT + tid];
    zsh[256 + tid] = d_z[b * TT + 256 + tid];
    __syncthreads();
    float lm = fmaxf(zsh[tid], zsh[tid + 256]);
    red[tid] = lm; __syncthreads();
    for (int s = 128; s > 0; s >>= 1) {
        if (tid < s) red[tid] = fmaxf(red[tid], red[tid + s]);
        __syncthreads();
    }
    float mx = red[0]; __syncthreads();
    float e0 = __expf(zsh[tid] - mx), e1 = __expf(zsh[tid + 256] - mx);
    red[tid] = e0 + e1; __syncthreads();
    for (int s = 128; s > 0; s >>= 1) {
        if (tid < s) red[tid] += red[tid + s];
        __syncthreads();
    }
    float inv = __fdividef(1.f, red[0]); __syncthreads();
    zsh[tid] = e0 * inv;
    zsh[tid + 256] = e1 * inv;
    __syncthreads();

    // r = sum_t a[t] * h[b][t][tid]  (coalesced over threads, unrolled over t)
    const float* hbp = d_h + (size_t)b * TT * DD + tid;
    float acc = 0.f;
#pragma unroll 8
    for (int t = 0; t < TT; t++)
        acc += zsh[t] * hbp[(size_t)t * DD];
    rsh[tid] = acc;
    hls[tid] = hbp[(size_t)(TT - 1) * DD];
    __syncthreads();

    // rr = tanh(r @ Wp.T + h_last @ Wx.T)
    float acc2 = 0.f;
    for (int d = 0; d < DD; d++)
        acc2 += rsh[d] * d_WpT[d * DD + tid] + hls[d] * d_WxT[d * DD + tid];
    rrsh[tid] = ftanhf(acc2);
    __syncthreads();

    // y = softmax(rr @ Wf.T + b_f)
    float lg = b_f[tid];
    for (int e = 0; e < DD; e++) lg += rrsh[e] * d_WfT[e * DD + tid];
    red[tid] = lg; __syncthreads();
    for (int s = 128; s > 0; s >>= 1) {
        if (tid < s) red[tid] = fmaxf(red[tid], red[tid + s]);
        __syncthreads();
    }
    float mx2 = red[0]; __syncthreads();
    float ex = __expf(lg - mx2);
    red[tid] = ex; __syncthreads();
    for (int s = 128; s > 0; s >>= 1) {
        if (tid < s) red[tid] += red[tid + s];
        __syncthreads();
    }
    out[b * DD + tid] = __fdividef(ex, red[0]);
}

// ---------------------------------------------------------------------------
extern "C" void kernel_launch(void* const* d_in, const int* in_sizes, int n_in,
                              void* d_out, int out_size) {
    const int*   x      = (const int*)d_in[0];
    const int*   s      = (const int*)d_in[1];
    const float* emb    = (const float*)d_in[2];
    const float* w_ih   = (const float*)d_in[3];
    const float* w_hh   = (const float*)d_in[4];
    const float* b_lstm = (const float*)d_in[5];
    const float* W_y    = (const float*)d_in[6];
    const float* w_t    = (const float*)d_in[7];
    const float* W_p    = (const float*)d_in[8];
    const float* W_x    = (const float*)d_in[9];
    const float* W_f    = (const float*)d_in[10];
    const float* b_f    = (const float*)d_in[11];
    float* out = (float*)d_out;

    const size_t lstm_smem = LSTM_SMEM_BYTES;
    const size_t att_smem  = (512 + 2 * 256 * 36 + 256) * sizeof(float);
    cudaFuncSetAttribute(k_lstm2, cudaFuncAttributeMaxDynamicSharedMemorySize,
                         (int)lstm_smem);
    cudaFuncSetAttribute(k_att, cudaFuncAttributeMaxDynamicSharedMemorySize,
                         (int)att_smem);

    k_prep<<<256, 256>>>(W_p, W_x, W_f);
    k_snorm<<<1, 256>>>(s, emb);
    k_xs<<<dim3(256, 8), 256>>>(x, emb, w_ih, b_lstm);
    k_lstm2<<<64, 256, lstm_smem>>>(w_hh);
    k_att<<<dim3(64, 16), 256, att_smem>>>(W_y, w_t);
    k_head<<<64, 256>>>(b_f, out);
}

// round 16
// speedup vs baseline: 2.3033x; 1.0433x over previous
#include <cuda_runtime.h>
#include <cstdint>
#include <cstddef>

typedef unsigned long long u64;

#define BB 64
#define TT 512
#define DD 256
#define GG 1024   // 4*D
#define CLS 8     // CTAs per cluster

// ---------------- scratch (device globals; no runtime allocation) ----------
__device__ float d_xs[(size_t)BB * TT * GG];
__device__ float d_h[(size_t)BB * TT * DD];
__device__ float d_snorm[BB * DD];
__device__ float d_WpT[DD * DD];
__device__ float d_WxT[DD * DD];
__device__ float d_WfT[DD * DD];
__device__ float d_z[BB * TT];

// ---------------- fast activations (MUFU.TANH) -------------------------------
__device__ __forceinline__ float ftanhf(float x) {
    float r; asm("tanh.approx.f32 %0, %1;" : "=f"(r) : "f"(x)); return r;
}
__device__ __forceinline__ float fsig(float x) {
    return fmaf(0.5f, ftanhf(0.5f * x), 0.5f);
}

__device__ __forceinline__ uint32_t ctarank() {
    uint32_t r; asm("mov.u32 %0, %%cluster_ctarank;" : "=r"(r)); return r;
}
__device__ __forceinline__ void cluster_sync() {
    asm volatile("barrier.cluster.arrive.aligned;\n\tbarrier.cluster.wait.aligned;" ::: "memory");
}
__device__ __forceinline__ uint32_t mapa_sh(uint32_t laddr, uint32_t rank) {
    uint32_t ra; asm("mapa.shared::cluster.u32 %0, %1, %2;" : "=r"(ra) : "r"(laddr), "r"(rank));
    return ra;
}
__device__ __forceinline__ void mbar_init(uint32_t addr, uint32_t cnt) {
    asm volatile("mbarrier.init.shared.b64 [%0], %1;" :: "r"(addr), "r"(cnt) : "memory");
}
__device__ __forceinline__ void mbar_expect(uint32_t addr, uint32_t bytes) {
    asm volatile("mbarrier.arrive.expect_tx.shared.b64 _, [%0], %1;"
                 :: "r"(addr), "r"(bytes) : "memory");
}
__device__ __forceinline__ void st_async_v4(uint32_t raddr, float4 v, uint32_t rmbar) {
    asm volatile(
        "st.async.shared::cluster.mbarrier::complete_tx::bytes.v4.b32 "
        "[%0], {%1,%2,%3,%4}, [%5];"
        :: "r"(raddr),
           "r"(__float_as_uint(v.x)), "r"(__float_as_uint(v.y)),
           "r"(__float_as_uint(v.z)), "r"(__float_as_uint(v.w)),
           "r"(rmbar) : "memory");
}
__device__ __forceinline__ void mbar_wait(uint32_t addr, uint32_t parity) {
    asm volatile(
        "{\n\t.reg .pred P;\n\t"
        "WL_%=:\n\t"
        "mbarrier.try_wait.parity.acquire.cluster.shared::cta.b64 P, [%0], %1, 0x989680;\n\t"
        "@!P bra WL_%=;\n\t"
        "}" :: "r"(addr), "r"(parity) : "memory");
}

// ---------------- packed f32x2 helpers --------------------------------------
__device__ __forceinline__ u64 dup2(float v) {
    u64 r; asm("mov.b64 %0, {%1, %1};" : "=l"(r) : "f"(v)); return r;
}
__device__ __forceinline__ void fma2(u64& d, u64 a, u64 b) {
    asm("fma.rn.f32x2 %0, %1, %2, %0;" : "+l"(d) : "l"(a), "l"(b));
}
__device__ __forceinline__ void up2(float& lo, float& hi, u64 v) {
    asm("mov.b64 {%0, %1}, %2;" : "=f"(lo), "=f"(hi) : "l"(v));
}

// ---------------- prep ------------------------------------------------------
__global__ void k_prep(const float* __restrict__ W_p,
                       const float* __restrict__ W_x, const float* __restrict__ W_f) {
    int i = blockIdx.x * 256 + threadIdx.x;
    if (i < DD * DD) {
        int e = i / DD, d = i % DD;
        d_WpT[d * DD + e] = W_p[i];
        d_WxT[d * DD + e] = W_x[i];
        d_WfT[d * DD + e] = W_f[i];
    }
}

// ---------------- s_norm ----------------------------------------------------
__global__ void k_snorm(const int* __restrict__ s, const float* __restrict__ emb) {
    int d = threadIdx.x;
    float sum = 0.f, sq = 0.f;
    for (int b = 0; b < BB; b++) {
        float v = emb[(size_t)s[b] * DD + d];
        sum += v; sq += v * v;
    }
    float mu  = sum * (1.f / BB);
    float var = sq * (1.f / BB) - mu * mu;
    float inv = rsqrtf(var + 1e-5f);
    for (int b = 0; b < BB; b++) {
        float v = emb[(size_t)s[b] * DD + d];
        d_snorm[b * DD + d] = (v - mu) * inv;
    }
}

// ---------------- xs = emb[x] @ w_ih.T + b  (128x128 tile, f32x2) -----------
__global__ void __launch_bounds__(256) k_xs(const int* __restrict__ x,
                                            const float* __restrict__ emb,
                                            const float* __restrict__ w_ih,
                                            const float* __restrict__ bl) {
    __shared__ float As[16][128];
    __shared__ float Bs[16][128];
    int tid = threadIdx.x;
    int m0 = blockIdx.x * 128, n0 = blockIdx.y * 128;
    int tx = tid & 15, ty = tid >> 4;

    int row_i = tid >> 1, kc = (tid & 1) * 8;
    int tok = x[m0 + row_i];
    const float* arow = emb + (size_t)tok * DD;
    const float* brow = w_ih + (size_t)(n0 + row_i) * DD;

    u64 acc2[8][4];
#pragma unroll
    for (int i = 0; i < 8; i++)
#pragma unroll
        for (int j = 0; j < 4; j++) acc2[i][j] = 0ull;

    for (int k0 = 0; k0 < DD; k0 += 16) {
        float4 a0 = *(const float4*)(arow + k0 + kc);
        float4 a1 = *(const float4*)(arow + k0 + kc + 4);
        float4 b0v = *(const float4*)(brow + k0 + kc);
        float4 b1v = *(const float4*)(brow + k0 + kc + 4);
        As[kc + 0][row_i] = a0.x; As[kc + 1][row_i] = a0.y;
        As[kc + 2][row_i] = a0.z; As[kc + 3][row_i] = a0.w;
        As[kc + 4][row_i] = a1.x; As[kc + 5][row_i] = a1.y;
        As[kc + 6][row_i] = a1.z; As[kc + 7][row_i] = a1.w;
        Bs[kc + 0][row_i] = b0v.x; Bs[kc + 1][row_i] = b0v.y;
        Bs[kc + 2][row_i] = b0v.z; Bs[kc + 3][row_i] = b0v.w;
        Bs[kc + 4][row_i] = b1v.x; Bs[kc + 5][row_i] = b1v.y;
        Bs[kc + 6][row_i] = b1v.z; Bs[kc + 7][row_i] = b1v.w;
        __syncthreads();
#pragma unroll
        for (int k = 0; k < 16; k++) {
            float4 a0v = *(const float4*)&As[k][ty * 8];
            float4 a1v = *(const float4*)&As[k][ty * 8 + 4];
            const ulonglong2* bp2 = (const ulonglong2*)&Bs[k][tx * 8];
            ulonglong2 bA = bp2[0], bB = bp2[1];
            float aa[8] = {a0v.x, a0v.y, a0v.z, a0v.w, a1v.x, a1v.y, a1v.z, a1v.w};
#pragma unroll
            for (int i = 0; i < 8; i++) {
                u64 ai = dup2(aa[i]);
                fma2(acc2[i][0], ai, bA.x);
                fma2(acc2[i][1], ai, bA.y);
                fma2(acc2[i][2], ai, bB.x);
                fma2(acc2[i][3], ai, bB.y);
            }
        }
        __syncthreads();
    }
    int col = n0 + tx * 8;
    float4 blv0 = *(const float4*)(bl + col);
    float4 blv1 = *(const float4*)(bl + col + 4);
#pragma unroll
    for (int i = 0; i < 8; i++) {
        size_t row = m0 + ty * 8 + i;
        float c0, c1, c2, c3, c4, c5, c6, c7;
        up2(c0, c1, acc2[i][0]);
        up2(c2, c3, acc2[i][1]);
        up2(c4, c5, acc2[i][2]);
        up2(c6, c7, acc2[i][3]);
        float* op = d_xs + row * GG + col;
        *(float4*)op       = make_float4(c0 + blv0.x, c1 + blv0.y, c2 + blv0.z, c3 + blv0.w);
        *(float4*)(op + 4) = make_float4(c4 + blv1.x, c5 + blv1.y, c6 + blv1.z, c7 + blv1.w);
    }
}

// ---------------- LSTM recurrence: R11 config (proven) -----------------------
#define OFF_PSMA  32768
#define OFF_PSMB  (32768 + 4096)
#define OFF_HB    (32768 + 8192)
#define OFF_HST   (OFF_HB + 4096)
#define OFF_MBAR  (OFF_HST + 256)
#define LSTM_SMEM_BYTES ((OFF_MBAR + 8) * 4)
#define PHASE_BYTES 4096u

__device__ __forceinline__ void lstm_mm(const float* hcur,
                                        const u64 (&wreg)[8][4][2],
                                        float* psm, int wid, int lane) {
    u64 acc2[2][4];
#pragma unroll
    for (int b = 0; b < 4; b++) { acc2[0][b] = 0ull; acc2[1][b] = 0ull; }
    const float* hp = hcur + wid * 32;
#pragma unroll
    for (int i4 = 0; i4 < 8; i4++) {
        float ha[4][4];
        *(float4*)ha[0] = *(const float4*)(hp + 0);
        *(float4*)ha[1] = *(const float4*)(hp + 256);
        *(float4*)ha[2] = *(const float4*)(hp + 512);
        *(float4*)ha[3] = *(const float4*)(hp + 768);
#pragma unroll
        for (int k = 0; k < 4; k++)
#pragma unroll
            for (int b = 0; b < 4; b++) {
                u64 hh = dup2(ha[b][k]);
                fma2(acc2[0][b], wreg[i4][k][0], hh);
                fma2(acc2[1][b], wreg[i4][k][1], hh);
            }
        hp += 4;
    }
#pragma unroll
    for (int b = 0; b < 4; b++) {
        float x0, x1, x2, x3;
        up2(x0, x1, acc2[0][b]);
        up2(x2, x3, acc2[1][b]);
        *(float4*)(psm + (wid * 4 + b) * 128 + lane * 4) = make_float4(x0, x1, x2, x3);
    }
}

__global__ void __launch_bounds__(256, 1) __cluster_dims__(CLS, 1, 1)
k_lstm2(const float* __restrict__ w_hh) {
    extern __shared__ float smem[];
    float* wsm  = smem;
    float* psmA = smem + OFF_PSMA;
    float* psmB = smem + OFF_PSMB;
    float* hbas = smem + OFF_HB;
    float* hstA = smem + OFF_HST;
    float* hstB = smem + OFF_HST + 128;

    int tid = threadIdx.x;
    uint32_t rank = ctarank();
    int b0 = (blockIdx.x >> 3) * 8;
    int wid = tid >> 5, lane = tid & 31;

    uint32_t smem_u32 = (uint32_t)__cvta_generic_to_shared(smem);
    uint32_t mbar_u32 = smem_u32 + OFF_MBAR * 4;
    uint32_t hb_u32   = smem_u32 + OFF_HB * 4;

    if (tid == 0) {
        mbar_init(mbar_u32 + 0,  1);
        mbar_init(mbar_u32 + 8,  1);
        mbar_init(mbar_u32 + 16, 1);
        mbar_init(mbar_u32 + 24, 1);
        mbar_expect(mbar_u32 + 0,  PHASE_BYTES);
        mbar_expect(mbar_u32 + 8,  PHASE_BYTES);
        mbar_expect(mbar_u32 + 16, PHASE_BYTES);
        mbar_expect(mbar_u32 + 24, PHASE_BYTES);
    }

    // stage weights
    {
        int jl = tid & 127, dh = tid >> 7;
        int jglob = (jl >> 5) * 256 + 32 * (int)rank + (jl & 31);
        const float* wrow = w_hh + (size_t)jglob * DD;
#pragma unroll 4
        for (int it = 0; it < 32; it++) {
            int d = dh * 128 + it * 4;
            float4 v = *(const float4*)(wrow + d);
            wsm[(d + 0) * 128 + jl] = v.x;
            wsm[(d + 1) * 128 + jl] = v.y;
            wsm[(d + 2) * 128 + jl] = v.z;
            wsm[(d + 3) * 128 + jl] = v.w;
        }
    }
    for (int i = tid; i < 4096; i += 256) hbas[i] = 0.f;
    __syncthreads();

    u64 wreg[8][4][2];
#pragma unroll
    for (int i4 = 0; i4 < 8; i4++)
#pragma unroll
        for (int k = 0; k < 4; k++) {
            const u64* wp2 = (const u64*)(wsm + (wid * 32 + i4 * 4 + k) * 128 + lane * 4);
            wreg[i4][k][0] = wp2[0];
            wreg[i4][k][1] = wp2[1];
        }
    cluster_sync();

    int tl   = tid & 127;
    int half = tid >> 7;
    int actb = tl >> 5;
    int actd = tl & 31;
    float c_reg = 0.f;
    int dglob = 32 * (int)rank + actd;
    int myb  = b0 + half * 4 + actb;

    uint32_t push_rem, poff0, poff1;
    int q0 = tl & 15, q1 = (tl & 15) + 16;
    uint32_t rmb0, rmb1;
    {
        uint32_t tr = (uint32_t)(tl >> 4);
        push_rem = mapa_sh(hb_u32, tr);
        poff0 = (uint32_t)(((q0 >> 3) * 256 + 32 * (int)rank + (q0 & 7) * 4) * 4);
        poff1 = (uint32_t)(((q1 >> 3) * 256 + 32 * (int)rank + (q1 & 7) * 4) * 4);
        rmb0 = mapa_sh(mbar_u32 + (uint32_t)(16 * half) + 0, tr);
        rmb1 = mapa_sh(mbar_u32 + (uint32_t)(16 * half) + 8, tr);
    }
    float* hst = half ? hstB : hstA;

    int phA0 = 0, phA1 = 0, phB0 = 0, phB1 = 0;

    for (int t = 0; t < TT; t++) {
        int bsel = t & 1;
        int nsel = bsel ^ 1;

        const float* xp = d_xs + ((size_t)myb * TT + t) * GG + dglob;
        float xg0 = xp[0], xg1 = xp[256], xg2 = xp[512], xg3 = xp[768];

        // ================= group A =================
        if (t > 0) {
            if (bsel) { mbar_wait(mbar_u32 + 8, (uint32_t)phA1); phA1 ^= 1; }
            else      { mbar_wait(mbar_u32 + 0, (uint32_t)phA0); phA0 ^= 1; }
            if (tid == 0) mbar_expect(mbar_u32 + (uint32_t)(8 * bsel), PHASE_BYTES);
        }
        lstm_mm(hbas + bsel * 1024, wreg, psmA, wid, lane);
        __syncthreads();

        if (half == 0) {
            float g4[4] = {xg0, xg1, xg2, xg3};
#pragma unroll
            for (int gm = 0; gm < 4; gm++) {
                int jl = gm * 32 + actd;
                float s = 0.f;
#pragma unroll
                for (int ds = 0; ds < 8; ds++)
                    s += psmA[(ds * 4 + actb) * 128 + jl];
                g4[gm] += s;
            }
            float ig = fsig(g4[0]), fg = fsig(g4[1]);
            float gg = ftanhf(g4[2]), og = fsig(g4[3]);
            c_reg = fg * c_reg + ig * gg;
            float hval = og * ftanhf(c_reg);
            d_h[((size_t)myb * TT + t) * DD + dglob] = hval;
            if (t + 1 < TT) {
                hst[actb * 32 + actd] = hval;
                asm volatile("bar.sync 1, 128;" ::: "memory");
                uint32_t dst = push_rem + (uint32_t)(nsel * 4096);
                uint32_t rmb = nsel ? rmb1 : rmb0;
                float4 v0 = *(const float4*)(hst + (q0 >> 3) * 32 + (q0 & 7) * 4);
                float4 v1 = *(const float4*)(hst + (q1 >> 3) * 32 + (q1 & 7) * 4);
                st_async_v4(dst + poff0, v0, rmb);
                st_async_v4(dst + poff1, v1, rmb);
            }
        }

        // ================= group B =================
        if (t > 0) {
            if (bsel) { mbar_wait(mbar_u32 + 24, (uint32_t)phB1); phB1 ^= 1; }
            else      { mbar_wait(mbar_u32 + 16, (uint32_t)phB0); phB0 ^= 1; }
            if (tid == 0) mbar_expect(mbar_u32 + 16 + (uint32_t)(8 * bsel), PHASE_BYTES);
        }
        lstm_mm(hbas + 2048 + bsel * 1024, wreg, psmB, wid, lane);
        __syncthreads();

        if (half == 1) {
            float g4[4] = {xg0, xg1, xg2, xg3};
#pragma unroll
            for (int gm = 0; gm < 4; gm++) {
                int jl = gm * 32 + actd;
                float s = 0.f;
#pragma unroll
                for (int ds = 0; ds < 8; ds++)
                    s += psmB[(ds * 4 + actb) * 128 + jl];
                g4[gm] += s;
            }
            float ig = fsig(g4[0]), fg = fsig(g4[1]);
            float gg = ftanhf(g4[2]), og = fsig(g4[3]);
            c_reg = fg * c_reg + ig * gg;
            float hval = og * ftanhf(c_reg);
            d_h[((size_t)myb * TT + t) * DD + dglob] = hval;
            if (t + 1 < TT) {
                hst[actb * 32 + actd] = hval;
                asm volatile("bar.sync 2, 128;" ::: "memory");
                uint32_t dst = push_rem + (uint32_t)(8192 + nsel * 4096);
                uint32_t rmb = nsel ? rmb1 : rmb0;
                float4 v0 = *(const float4*)(hst + (q0 >> 3) * 32 + (q0 & 7) * 4);
                float4 v1 = *(const float4*)(hst + (q1 >> 3) * 32 + (q1 & 7) * 4);
                st_async_v4(dst + poff0, v0, rmb);
                st_async_v4(dst + poff1, v1, rmb);
            }
        }
    }
}

// ---- correlation + Y + z, register-blocked 2n x 16r per thread --------------
// thread: np = tid & 127 (columns 2np, 2np+1), rh = tid >> 7 (rows rh*16..+16)
__global__ void __launch_bounds__(256) k_att(const float* __restrict__ W_y,
                                             const float* __restrict__ w_t) {
    extern __shared__ float sm[];
    float* sdup = sm;               // 512
    float* bufT = sm + 512;         // [256 d][36] (32 r used)
    float* mT   = sm + 512 + 9216;  // [256 n][36]
    float* zp   = sm + 512 + 18432; // [8 warps][32 r]

    int b = blockIdx.x;
    int t0 = blockIdx.y * 32;
    int tid = threadIdx.x;
    int np = tid & 127;
    int rh = tid >> 7;
    int n0 = np * 2;
    int rbase = rh * 16;

    float sv0 = d_snorm[b * DD + tid];
    sdup[tid] = sv0;
    sdup[DD + tid] = sv0;

    const float* hrow = d_h + ((size_t)b * TT + t0) * DD + tid;
#pragma unroll 4
    for (int r = 0; r < 32; r++)
        bufT[tid * 36 + r] = hrow[(size_t)r * DD];
    __syncthreads();

    // stage 1: m[r][n] = sum_d h[r][d] * s_norm[d+n], 2 n x 8 r-pairs
    u64 mm2[2][8];
#pragma unroll
    for (int n = 0; n < 2; n++)
#pragma unroll
        for (int rp = 0; rp < 8; rp++) mm2[n][rp] = 0ull;
#pragma unroll 4
    for (int d = 0; d < DD; d++) {
        u64 s20 = dup2(sdup[d + n0]);
        u64 s21 = dup2(sdup[d + n0 + 1]);
        const ulonglong2* bp = (const ulonglong2*)(bufT + d * 36 + rbase);
        ulonglong2 v0 = bp[0], v1 = bp[1];
#pragma unroll
        for (int q = 0; q < 2; q++) {
            u64 a = q ? v1.x : v0.x;
            u64 c = q ? v1.y : v0.y;
            fma2(mm2[0][2 * q + 0], a, s20);
            fma2(mm2[0][2 * q + 1], c, s20);
            fma2(mm2[1][2 * q + 0], a, s21);
            fma2(mm2[1][2 * q + 1], c, s21);
        }
        bp += 2;
        ulonglong2 v2 = bp[0], v3 = bp[1];
#pragma unroll
        for (int q = 0; q < 2; q++) {
            u64 a = q ? v3.x : v2.x;
            u64 c = q ? v3.y : v2.y;
            fma2(mm2[0][4 + 2 * q + 0], a, s20);
            fma2(mm2[0][4 + 2 * q + 1], c, s20);
            fma2(mm2[1][4 + 2 * q + 0], a, s21);
            fma2(mm2[1][4 + 2 * q + 1], c, s21);
        }
    }
    // store to mT[n][r]
#pragma unroll
    for (int n = 0; n < 2; n++) {
        ulonglong2* mtp = (ulonglong2*)(mT + (n0 + n) * 36 + rbase);
        ulonglong2 w0, w1;
        w0.x = mm2[n][0]; w0.y = mm2[n][1];
        w1.x = mm2[n][2]; w1.y = mm2[n][3];
        mtp[0] = w0; mtp[1] = w1;
        w0.x = mm2[n][4]; w0.y = mm2[n][5];
        w1.x = mm2[n][6]; w1.y = mm2[n][7];
        mtp[2] = w0; mtp[3] = w1;
    }
    __syncthreads();

    // stage 2: Y[r][n] = sum_d m[r][d] * W_y[d][n]
    u64 yy2[2][8];
#pragma unroll
    for (int n = 0; n < 2; n++)
#pragma unroll
        for (int rp = 0; rp < 8; rp++) yy2[n][rp] = 0ull;
#pragma unroll 4
    for (int d = 0; d < DD; d++) {
        float2 wv = *(const float2*)(W_y + d * DD + n0);
        u64 w20 = dup2(wv.x);
        u64 w21 = dup2(wv.y);
        const ulonglong2* mp = (const ulonglong2*)(mT + d * 36 + rbase);
        ulonglong2 v0 = mp[0], v1 = mp[1], v2 = mp[2], v3 = mp[3];
        u64 rr[8] = {v0.x, v0.y, v1.x, v1.y, v2.x, v2.y, v3.x, v3.y};
#pragma unroll
        for (int rp = 0; rp < 8; rp++) {
            fma2(yy2[0][rp], rr[rp], w20);
            fma2(yy2[1][rp], rr[rp], w21);
        }
    }

    // epilogue: v[r] = sum_n tanh(Y[r][n]) * w_t[n]
    float2 wtv = *(const float2*)(w_t + n0);
    int lane = tid & 31, wrp = tid >> 5;
#pragma unroll
    for (int rp = 0; rp < 8; rp++) {
        float y00, y01, y10, y11;
        up2(y00, y01, yy2[0][rp]);
        up2(y10, y11, yy2[1][rp]);
        float v0 = ftanhf(y00) * wtv.x + ftanhf(y10) * wtv.y;
        float v1 = ftanhf(y01) * wtv.x + ftanhf(y11) * wtv.y;
        v0 += __shfl_down_sync(0xffffffffu, v0, 16);
        v1 += __shfl_down_sync(0xffffffffu, v1, 16);
        v0 += __shfl_down_sync(0xffffffffu, v0, 8);
        v1 += __shfl_down_sync(0xffffffffu, v1, 8);
        v0 += __shfl_down_sync(0xffffffffu, v0, 4);
        v1 += __shfl_down_sync(0xffffffffu, v1, 4);
        v0 += __shfl_down_sync(0xffffffffu, v0, 2);
        v1 += __shfl_down_sync(0xffffffffu, v1, 2);
        v0 += __shfl_down_sync(0xffffffffu, v0, 1);
        v1 += __shfl_down_sync(0xffffffffu, v1, 1);
        if (lane == 0) {
            zp[wrp * 32 + rbase + 2 * rp + 0] = v0;
            zp[wrp * 32 + rbase + 2 * rp + 1] = v1;
        }
    }
    __syncthreads();
    if (tid < 32) {
        int r = tid;
        int wbase = (r < 16) ? 0 : 4;
        float sacc = zp[(wbase + 0) * 32 + r] + zp[(wbase + 1) * 32 + r]
                   + zp[(wbase + 2) * 32 + r] + zp[(wbase + 3) * 32 + r];
        d_z[b * TT + t0 + r] = sacc;
    }
}

// ---- fused head: softmax(z) -> r = sum a*h -> final MLP + softmax ----------
__global__ void __launch_bounds__(256) k_head(const float* __restrict__ b_f,
                                              float* __restrict__ out) {
    int b = blockIdx.x, tid = threadIdx.x;
    __shared__ float zsh[TT];
    __shared__ float red[256];
    __shared__ float rsh[DD], hls[DD], rrsh[DD];

    zsh[tid] = d_z[b * TT + tid];
    zsh[256 + tid] = d_z[b * TT + 256 + tid];
    __syncthreads();
    float lm = fmaxf(zsh[tid], zsh[tid + 256]);
    red[tid] = lm; __syncthreads();
    for (int s = 128; s > 0; s >>= 1) {
        if (tid < s) red[tid] = fmaxf(red[tid], red[tid + s]);
        __syncthreads();
    }
    float mx = red[0]; __syncthreads();
    float e0 = __expf(zsh[tid] - mx), e1 = __expf(zsh[tid + 256] - mx);
    red[tid] = e0 + e1; __syncthreads();
    for (int s = 128; s > 0; s >>= 1) {
        if (tid < s) red[tid] += red[tid + s];
        __syncthreads();
    }
    float inv = __fdividef(1.f, red[0]); __syncthreads();
    zsh[tid] = e0 * inv;
    zsh[tid + 256] = e1 * inv;
    __syncthreads();

    const float* hbp = d_h + (size_t)b * TT * DD + tid;
    float acc = 0.f;
#pragma unroll 8
    for (int t = 0; t < TT; t++)
        acc += zsh[t] * hbp[(size_t)t * DD];
    rsh[tid] = acc;
    hls[tid] = hbp[(size_t)(TT - 1) * DD];
    __syncthreads();

    float acc2 = 0.f;
    for (int d = 0; d < DD; d++)
        acc2 += rsh[d] * d_WpT[d * DD + tid] + hls[d] * d_WxT[d * DD + tid];
    rrsh[tid] = ftanhf(acc2);
    __syncthreads();

    float lg = b_f[tid];
    for (int e = 0; e < DD; e++) lg += rrsh[e] * d_WfT[e * DD + tid];
    red[tid] = lg; __syncthreads();
    for (int s = 128; s > 0; s >>= 1) {
        if (tid < s) red[tid] = fmaxf(red[tid], red[tid + s]);
        __syncthreads();
    }
    float mx2 = red[0]; __syncthreads();
    float ex = __expf(lg - mx2);
    red[tid] = ex; __syncthreads();
    for (int s = 128; s > 0; s >>= 1) {
        if (tid < s) red[tid] += red[tid + s];
        __syncthreads();
    }
    out[b * DD + tid] = __fdividef(ex, red[0]);
}

// ---------------------------------------------------------------------------
extern "C" void kernel_launch(void* const* d_in, const int* in_sizes, int n_in,
                              void* d_out, int out_size) {
    const int*   x      = (const int*)d_in[0];
    const int*   s      = (const int*)d_in[1];
    const float* emb    = (const float*)d_in[2];
    const float* w_ih   = (const float*)d_in[3];
    const float* w_hh   = (const float*)d_in[4];
    const float* b_lstm = (const float*)d_in[5];
    const float* W_y    = (const float*)d_in[6];
    const float* w_t    = (const float*)d_in[7];
    const float* W_p    = (const float*)d_in[8];
    const float* W_x    = (const float*)d_in[9];
    const float* W_f    = (const float*)d_in[10];
    const float* b_f    = (const float*)d_in[11];
    float* out = (float*)d_out;

    const size_t lstm_smem = LSTM_SMEM_BYTES;
    const size_t att_smem  = (512 + 2 * 256 * 36 + 256) * sizeof(float);
    cudaFuncSetAttribute(k_lstm2, cudaFuncAttributeMaxDynamicSharedMemorySize,
                         (int)lstm_smem);
    cudaFuncSetAttribute(k_att, cudaFuncAttributeMaxDynamicSharedMemorySize,
                         (int)att_smem);

    k_prep<<<256, 256>>>(W_p, W_x, W_f);
    k_snorm<<<1, 256>>>(s, emb);
    k_xs<<<dim3(256, 8), 256>>>(x, emb, w_ih, b_lstm);
    k_lstm2<<<64, 256, lstm_smem>>>(w_hh);
    k_att<<<dim3(64, 16), 256, att_smem>>>(W_y, w_t);
    k_head<<<64, 256>>>(b_f, out);
}